// round 2
// baseline (speedup 1.0000x reference)
#include <cuda_runtime.h>
#include <math.h>

// ---------------------------------------------------------------------------
// LinearAutoregressiveHMM — round 2 (resubmit of r1 after infra failure):
// fp32 SIMT baseline, fully fused math.
//
// Pipeline:
//   prep_kernel   : softmax/log of transition+init, next[] argmax chain table,
//                   covar build -> Cholesky -> triangular inverse IC,
//                   logdet, m' = IC @ mean                (1 block, tiny)
//   wp_kernel     : W' = IC @ W  (K,C,F)                  (268 MFLOP)
//   gemm_elp_kernel: v = W'@x via Toeplitz A panels in smem; epilogue computes
//                   u = IC@e - m', quad = ||u - v||^2, writes elp (B,L,K)
//                   (137 GFLOP — the dominant cost)
//   forward_kernel: HMM logsumexp scan over L=64, argmax, state chain
//   pred_kernel   : 16-step AR loop, one block per batch, circular window
// ---------------------------------------------------------------------------

#define K_ST   8
#define LSEQ   64
#define CDIM   64
#define BATCH  512
#define PRED   16
#define FDIM   4096      // LSEQ*CDIM
#define ASTR   65        // padded smem row stride for A panels

// Scratch (static __device__ — no allocations allowed)
__device__ float d_Wp[K_ST * CDIM * FDIM];     // 8 MB : W' = IC @ W
__device__ float d_IC[K_ST * CDIM * CDIM];     // chol^{-1}
__device__ float d_mp[K_ST * CDIM];            // IC @ mean
__device__ float d_logdet[K_ST];               // sum log diag(chol)
__device__ float d_lt[K_ST * K_ST];            // log(softmax(trans)+1e-8)
__device__ float d_linit[K_ST];                // log softmax(init)
__device__ int   d_next[K_ST];                 // argmax of each trans row
__device__ float d_elp[BATCH * LSEQ * K_ST];   // 1 MB
__device__ int   d_states[BATCH * PRED];

// ---------------------------------------------------------------------------
// prep: all the small per-state math. One block of 256 threads, loops k=0..7.
// ---------------------------------------------------------------------------
__global__ void prep_kernel(const float* __restrict__ tm,
                            const float* __restrict__ initd,
                            const float* __restrict__ cchol,
                            const float* __restrict__ means)
{
    __shared__ float T[CDIM * CDIM];   // 16 KB (tril / later IC)
    __shared__ float Cv[CDIM * CDIM];  // 16 KB (covar / later chol)
    int tid = threadIdx.x;

    // transition softmax rows -> log_trans, next[]
    if (tid < K_ST) {
        float row[K_ST];
        float m = -1e30f;
        for (int j = 0; j < K_ST; ++j) { row[j] = tm[tid * K_ST + j]; m = fmaxf(m, row[j]); }
        float s = 0.f;
        for (int j = 0; j < K_ST; ++j) s += expf(row[j] - m);
        float lse = m + logf(s);
        for (int j = 0; j < K_ST; ++j)
            d_lt[tid * K_ST + j] = logf(expf(row[j] - lse) + 1e-8f);
        int arg = 0; float best = row[0];
        for (int j = 1; j < K_ST; ++j) if (row[j] > best) { best = row[j]; arg = j; }
        d_next[tid] = arg;
    }
    if (tid == 8) {
        float m = -1e30f;
        for (int j = 0; j < K_ST; ++j) m = fmaxf(m, initd[j]);
        float s = 0.f;
        for (int j = 0; j < K_ST; ++j) s += expf(initd[j] - m);
        float lse = m + logf(s);
        for (int j = 0; j < K_ST; ++j) d_linit[j] = initd[j] - lse;
    }

    for (int k = 0; k < K_ST; ++k) {
        __syncthreads();
        // T = tril(covar_chol[k]) with exp(diag)
        for (int idx = tid; idx < CDIM * CDIM; idx += 256) {
            int i = idx >> 6, j = idx & 63;
            float v = cchol[k * CDIM * CDIM + idx];
            T[idx] = (j > i) ? 0.f : (j == i ? expf(v) : v);
        }
        __syncthreads();
        // Cv = T T^T + 1e-6 I
        for (int idx = tid; idx < CDIM * CDIM; idx += 256) {
            int i = idx >> 6, j = idx & 63;
            int mmax = (i < j) ? i : j;
            float s = (i == j) ? 1e-6f : 0.f;
            for (int m = 0; m <= mmax; ++m) s += T[i * 64 + m] * T[j * 64 + m];
            Cv[idx] = s;
        }
        __syncthreads();
        // in-place Cholesky (lower) of Cv
        for (int c = 0; c < CDIM; ++c) {
            if (tid == 0) Cv[c * 64 + c] = sqrtf(Cv[c * 64 + c]);
            __syncthreads();
            float dinv = 1.f / Cv[c * 64 + c];
            for (int i = c + 1 + tid; i < CDIM; i += 256) Cv[i * 64 + c] *= dinv;
            __syncthreads();
            for (int idx = tid; idx < CDIM * CDIM; idx += 256) {
                int i = idx >> 6, m = idx & 63;
                if (i > c && m > c && m <= i)
                    Cv[i * 64 + m] -= Cv[i * 64 + c] * Cv[m * 64 + c];
            }
            __syncthreads();
        }
        if (tid == 0) {
            float s = 0.f;
            for (int i = 0; i < CDIM; ++i) s += logf(Cv[i * 64 + i]);
            d_logdet[k] = s;
        }
        // invert lower-triangular chol into T (T = chol^{-1})
        for (int idx = tid; idx < CDIM * CDIM; idx += 256) T[idx] = 0.f;
        __syncthreads();
        if (tid < CDIM) {
            int c = tid;
            T[c * 64 + c] = 1.f / Cv[c * 64 + c];
            for (int i = c + 1; i < CDIM; ++i) {
                float s = 0.f;
                for (int m = c; m < i; ++m) s += Cv[i * 64 + m] * T[m * 64 + c];
                T[i * 64 + c] = -s / Cv[i * 64 + i];
            }
        }
        __syncthreads();
        for (int idx = tid; idx < CDIM * CDIM; idx += 256)
            d_IC[k * CDIM * CDIM + idx] = T[idx];
        if (tid < CDIM) {
            float s = 0.f;
            for (int j = 0; j < CDIM; ++j) s += T[tid * 64 + j] * means[k * CDIM + j];
            d_mp[k * CDIM + tid] = s;
        }
        __syncthreads();
    }
}

// ---------------------------------------------------------------------------
// W' = IC @ W : grid (c=64, k=8), 256 threads, float4 streamed.
// ---------------------------------------------------------------------------
__global__ void wp_kernel(const float* __restrict__ W)
{
    int c = blockIdx.x, k = blockIdx.y;
    __shared__ float icr[CDIM];
    if (threadIdx.x < CDIM)
        icr[threadIdx.x] = d_IC[k * CDIM * CDIM + c * CDIM + threadIdx.x];
    __syncthreads();
    const float4* W4 = (const float4*)(W + (size_t)k * CDIM * FDIM);
    float4* O4 = (float4*)(d_Wp + (size_t)k * CDIM * FDIM + c * FDIM);
    for (int f4 = threadIdx.x; f4 < FDIM / 4; f4 += 256) {
        float4 acc = make_float4(0.f, 0.f, 0.f, 0.f);
        #pragma unroll 8
        for (int c2 = 0; c2 < CDIM; ++c2) {
            float ic = icr[c2];
            float4 wv = W4[c2 * (FDIM / 4) + f4];
            acc.x += ic * wv.x; acc.y += ic * wv.y;
            acc.z += ic * wv.z; acc.w += ic * wv.w;
        }
        O4[f4] = acc;
    }
}

// ---------------------------------------------------------------------------
// Big GEMM + elp epilogue.
// Block = (batch pair bx, state k). M=128 (2 batches x 64 t), N=64, K=4096.
// A panels (Toeplitz slices of zero-padded emissions) live in smem, reused
// across the whole K loop. B tiles are loaded transposed for LDS.128 b-frags.
// ---------------------------------------------------------------------------
extern __shared__ float smem_g[];
#define GEMM_SMEM_FLOATS (2 * 128 * ASTR + 64 * 64)
#define GEMM_SMEM_BYTES  (GEMM_SMEM_FLOATS * 4)

__global__ __launch_bounds__(256, 2) void gemm_elp_kernel(const float* __restrict__ em)
{
    float* As = smem_g;                 // [2][128][ASTR]
    float* Bs = smem_g + 2 * 128 * ASTR; // [64][64] (B^T tile / later IC^T)
    int tid = threadIdx.x;
    int bx = blockIdx.x, k = blockIdx.y;
    int b0 = bx * 2;

    // zero pad rows [0,64) of both panels
    for (int idx = tid; idx < 2 * 64 * 64; idx += 256) {
        int ba = idx >> 12; int r = (idx >> 6) & 63; int c = idx & 63;
        As[ba * 128 * ASTR + r * ASTR + c] = 0.f;
    }
    // load emissions rows into panel rows [64,128)
    for (int idx = tid; idx < 2 * 64 * 16; idx += 256) {
        int ba = idx >> 10; int r = (idx >> 4) & 63; int q = idx & 15;
        float4 v = *(const float4*)(em + (((size_t)(b0 + ba)) * 64 + r) * 64 + q * 4);
        float* dst = As + ba * 128 * ASTR + (64 + r) * ASTR + q * 4;
        dst[0] = v.x; dst[1] = v.y; dst[2] = v.z; dst[3] = v.w;
    }

    int ty = tid >> 4, tx = tid & 15;
    int batch = ty >> 3;
    int tbase = (ty & 7) * 8;
    int c0 = tx * 4;
    const float* aB = As + batch * 128 * ASTR + tbase * ASTR;

    float D[8][4];
    #pragma unroll
    for (int i = 0; i < 8; ++i)
        #pragma unroll
        for (int c = 0; c < 4; ++c) D[i][c] = 0.f;

    const float* Wk = d_Wp + (size_t)k * CDIM * FDIM;
    for (int j = 0; j < 64; ++j) {
        __syncthreads();
        // load B^T tile: Bs[kk][c] = W'[k][c][j*64+kk]
        for (int idx = tid; idx < 1024; idx += 256) {
            int c = idx >> 4, q = idx & 15;
            float4 v = *(const float4*)(Wk + c * FDIM + j * 64 + q * 4);
            Bs[(q * 4 + 0) * 64 + c] = v.x;
            Bs[(q * 4 + 1) * 64 + c] = v.y;
            Bs[(q * 4 + 2) * 64 + c] = v.z;
            Bs[(q * 4 + 3) * 64 + c] = v.w;
        }
        __syncthreads();
        const float* aj = aB + j * ASTR;
        #pragma unroll 8
        for (int kk = 0; kk < 64; ++kk) {
            float4 bv = *(const float4*)(Bs + kk * 64 + c0);
            #pragma unroll
            for (int i = 0; i < 8; ++i) {
                float a = aj[i * ASTR + kk];
                D[i][0] += a * bv.x; D[i][1] += a * bv.y;
                D[i][2] += a * bv.z; D[i][3] += a * bv.w;
            }
        }
    }

    // epilogue: u = IC@e - m', sol = u - v, quad, elp
    __syncthreads();
    const float* ICk = d_IC + k * CDIM * CDIM;
    for (int idx = tid; idx < CDIM * CDIM; idx += 256)
        Bs[(idx & 63) * 64 + (idx >> 6)] = ICk[idx];   // IC^T
    __syncthreads();

    float4 mpv = *(const float4*)(d_mp + k * CDIM + c0);
    float ldk = d_logdet[k];
    const float C_LOG2PI = 64.f * 1.8378770664093453f;

    for (int i = 0; i < 8; ++i) {
        int t = tbase + i;
        const float* erow = As + batch * 128 * ASTR + (64 + t) * ASTR;
        float ux = 0.f, uy = 0.f, uz = 0.f, uw = 0.f;
        #pragma unroll 8
        for (int c2 = 0; c2 < CDIM; ++c2) {
            float e = erow[c2];
            float4 icv = *(const float4*)(Bs + c2 * 64 + c0);
            ux += icv.x * e; uy += icv.y * e;
            uz += icv.z * e; uw += icv.w * e;
        }
        float sx = ux - mpv.x - D[i][0];
        float sy = uy - mpv.y - D[i][1];
        float sz = uz - mpv.z - D[i][2];
        float sw = uw - mpv.w - D[i][3];
        float part = sx * sx + sy * sy + sz * sz + sw * sw;
        part += __shfl_down_sync(0xffffffffu, part, 8, 16);
        part += __shfl_down_sync(0xffffffffu, part, 4, 16);
        part += __shfl_down_sync(0xffffffffu, part, 2, 16);
        part += __shfl_down_sync(0xffffffffu, part, 1, 16);
        if (tx == 0)
            d_elp[(((size_t)(b0 + batch)) * 64 + t) * 8 + k] =
                -0.5f * (C_LOG2PI + part) - ldk;
    }
}

// ---------------------------------------------------------------------------
// HMM forward scan + state chain. One thread per batch.
// ---------------------------------------------------------------------------
__global__ void forward_kernel()
{
    __shared__ float lt_s[K_ST * K_ST];
    int tid = threadIdx.x;
    if (tid < K_ST * K_ST) lt_s[tid] = d_lt[tid];
    __syncthreads();
    int b = blockIdx.x * blockDim.x + tid;
    if (b >= BATCH) return;

    const float* e = d_elp + (size_t)b * LSEQ * K_ST;
    float la[K_ST];
    for (int k = 0; k < K_ST; ++k) la[k] = d_linit[k] + e[k];
    for (int t = 1; t < LSEQ; ++t) {
        const float* et = e + t * K_ST;
        float nla[K_ST];
        for (int k = 0; k < K_ST; ++k) {
            float m = -1e30f;
            for (int j = 0; j < K_ST; ++j) m = fmaxf(m, la[j] + lt_s[j * K_ST + k]);
            float s = 0.f;
            for (int j = 0; j < K_ST; ++j) s += expf(la[j] + lt_s[j * K_ST + k] - m);
            nla[k] = m + logf(s) + et[k];
        }
        for (int k = 0; k < K_ST; ++k) la[k] = nla[k];
    }
    int arg = 0; float best = la[0];
    for (int k = 1; k < K_ST; ++k) if (la[k] > best) { best = la[k]; arg = k; }
    int s = d_next[arg];
    for (int p = 0; p < PRED; ++p) {
        d_states[b * PRED + p] = s;
        s = d_next[s];
    }
}

// ---------------------------------------------------------------------------
// AR prediction loop. One block per batch; circular 64-frame window in smem.
// ---------------------------------------------------------------------------
__global__ __launch_bounds__(256) void pred_kernel(const float* __restrict__ em,
                                                   const float* __restrict__ W,
                                                   const float* __restrict__ means,
                                                   float* __restrict__ out)
{
    __shared__ float buf[LSEQ * CDIM];   // 16 KB window
    __shared__ float predbuf[CDIM];
    int b = blockIdx.x;
    int tid = threadIdx.x;
    int w = tid >> 5, lane = tid & 31;

    {   // init window with emissions[b]
        float4* b4 = (float4*)buf;
        const float4* e4 = (const float4*)(em + (size_t)b * FDIM);
        for (int i = tid; i < FDIM / 4; i += 256) b4[i] = e4[i];
    }
    __syncthreads();

    for (int p = 0; p < PRED; ++p) {
        int s = d_states[b * PRED + p];
        const float* Ws = W + (size_t)s * CDIM * FDIM;
        for (int ci = 0; ci < 8; ++ci) {
            int c = w * 8 + ci;
            const float4* wr = (const float4*)(Ws + c * FDIM);
            float acc = 0.f;
            for (int f4 = lane; f4 < FDIM / 4; f4 += 32) {
                float4 wv = wr[f4];
                int j = f4 >> 4; int cq = f4 & 15;
                float4 xv = *(const float4*)(buf + (((p + j) & 63) << 6) + (cq << 2));
                acc += wv.x * xv.x + wv.y * xv.y + wv.z * xv.z + wv.w * xv.w;
            }
            acc += __shfl_down_sync(0xffffffffu, acc, 16);
            acc += __shfl_down_sync(0xffffffffu, acc, 8);
            acc += __shfl_down_sync(0xffffffffu, acc, 4);
            acc += __shfl_down_sync(0xffffffffu, acc, 2);
            acc += __shfl_down_sync(0xffffffffu, acc, 1);
            if (lane == 0) predbuf[c] = acc + means[s * CDIM + c];
        }
        __syncthreads();
        if (tid < CDIM) {
            float v = predbuf[tid];
            out[(((size_t)b) * PRED + p) * CDIM + tid] = v;
            buf[p * CDIM + tid] = v;   // p < 16 < 64, no wrap
        }
        __syncthreads();
    }
}

// ---------------------------------------------------------------------------
extern "C" void kernel_launch(void* const* d_in, const int* in_sizes, int n_in,
                              void* d_out, int out_size)
{
    const float* em    = (const float*)d_in[0];  // (512,64,64)
    const float* tm    = (const float*)d_in[1];  // (8,8)
    const float* initd = (const float*)d_in[2];  // (8,)
    const float* means = (const float*)d_in[3];  // (8,64)
    const float* cchol = (const float*)d_in[4];  // (8,64,64)
    const float* W     = (const float*)d_in[5];  // (8,64,4096)
    float* out = (float*)d_out;

    cudaFuncSetAttribute(gemm_elp_kernel,
                         cudaFuncAttributeMaxDynamicSharedMemorySize,
                         GEMM_SMEM_BYTES);

    prep_kernel<<<1, 256>>>(tm, initd, cchol, means);
    wp_kernel<<<dim3(64, 8), 256>>>(W);
    gemm_elp_kernel<<<dim3(256, 8), 256, GEMM_SMEM_BYTES>>>(em);
    forward_kernel<<<2, 256>>>();
    pred_kernel<<<512, 256>>>(em, W, means, out);
}

// round 5
// speedup vs baseline: 2.2719x; 2.2719x over previous
#include <cuda_runtime.h>
#include <math.h>
#include <stdint.h>

// ---------------------------------------------------------------------------
// LinearAutoregressiveHMM — round 5 (resubmit of r4 after broker failure):
// tf32 mma.sync (sm_100 non-'a' target).
//  elp GEMM: D = IC*e - (IC*W)*x via Toeplitz smem A panel, K=4160, 1-term tf32
//  pred:     batches grouped by s0 chain; 16 sequential grouped GEMM steps,
//            3-term tf32 split for full output accuracy.
// ---------------------------------------------------------------------------

#define K_ST   8
#define LSEQ   64
#define CDIM   64
#define BATCH  512
#define PRED   16
#define FDIM   4096
#define AST    68            // padded smem row stride (floats)

// static scratch
__device__ float d_Wn  [K_ST * CDIM * FDIM];   // 8 MB : tf32(-(IC@W))
__device__ float d_ICt [K_ST * CDIM * CDIM];   // tf32(IC)
__device__ float d_IC  [K_ST * CDIM * CDIM];
__device__ float d_mp  [K_ST * CDIM];
__device__ float d_logdet[K_ST];
__device__ float d_lt  [K_ST * K_ST];
__device__ float d_linit[K_ST];
__device__ int   d_next[K_ST];
__device__ float d_elp [BATCH * LSEQ * K_ST];
__device__ int   d_states[BATCH * PRED];
__device__ float d_Wphi[K_ST * CDIM * FDIM];   // 8 MB : tf32 hi of W
__device__ float d_Wplo[K_ST * CDIM * FDIM];   // 8 MB : tf32 lo of W
__device__ float d_winhi[BATCH * 80 * CDIM];   // sliding windows (hi)
__device__ float d_winlo[BATCH * 80 * CDIM];   // (lo)
__device__ int   d_perm[BATCH];
__device__ int   d_goff[K_ST];
__device__ int   d_gcnt[K_ST];
__device__ int   d_chain[K_ST * PRED];

// ---------------------------------------------------------------------------
__device__ __forceinline__ float tf32r(float x) {
    uint32_t u;
    asm("cvt.rna.tf32.f32 %0, %1;" : "=r"(u) : "f"(x));
    return __uint_as_float(u);
}
__device__ __forceinline__ uint32_t smem_u32(const void* p) {
    uint32_t a;
    asm("{ .reg .u64 t; cvta.to.shared.u64 t, %1; cvt.u32.u64 %0, t; }"
        : "=r"(a) : "l"(p));
    return a;
}
__device__ __forceinline__ void cpa16(uint32_t dst, const void* src) {
    asm volatile("cp.async.cg.shared.global [%0], [%1], 16;" :: "r"(dst), "l"(src));
}
#define CP_COMMIT() asm volatile("cp.async.commit_group;" ::: "memory")
#define CP_WAIT1()  asm volatile("cp.async.wait_group 1;" ::: "memory")
#define CP_WAIT0()  asm volatile("cp.async.wait_group 0;" ::: "memory")

__device__ __forceinline__ void mma8(float c[4], const uint32_t a[4],
                                     uint32_t b0, uint32_t b1) {
    asm volatile(
        "mma.sync.aligned.m16n8k8.row.col.f32.tf32.tf32.f32 "
        "{%0,%1,%2,%3},{%4,%5,%6,%7},{%8,%9},{%0,%1,%2,%3};"
        : "+f"(c[0]), "+f"(c[1]), "+f"(c[2]), "+f"(c[3])
        : "r"(a[0]), "r"(a[1]), "r"(a[2]), "r"(a[3]), "r"(b0), "r"(b1));
}

// ---------------------------------------------------------------------------
// prep: small per-state math (softmax, Cholesky, inverse, logdet, mp)
// ---------------------------------------------------------------------------
__global__ void prep_kernel(const float* __restrict__ tm,
                            const float* __restrict__ initd,
                            const float* __restrict__ cchol,
                            const float* __restrict__ means)
{
    __shared__ float T[CDIM * CDIM];
    __shared__ float Cv[CDIM * CDIM];
    int tid = threadIdx.x;

    if (tid < K_ST) {
        float row[K_ST];
        float m = -1e30f;
        for (int j = 0; j < K_ST; ++j) { row[j] = tm[tid * K_ST + j]; m = fmaxf(m, row[j]); }
        float s = 0.f;
        for (int j = 0; j < K_ST; ++j) s += expf(row[j] - m);
        float lse = m + logf(s);
        for (int j = 0; j < K_ST; ++j)
            d_lt[tid * K_ST + j] = logf(expf(row[j] - lse) + 1e-8f);
        int arg = 0; float best = row[0];
        for (int j = 1; j < K_ST; ++j) if (row[j] > best) { best = row[j]; arg = j; }
        d_next[tid] = arg;
    }
    if (tid == 8) {
        float m = -1e30f;
        for (int j = 0; j < K_ST; ++j) m = fmaxf(m, initd[j]);
        float s = 0.f;
        for (int j = 0; j < K_ST; ++j) s += expf(initd[j] - m);
        float lse = m + logf(s);
        for (int j = 0; j < K_ST; ++j) d_linit[j] = initd[j] - lse;
    }

    for (int k = 0; k < K_ST; ++k) {
        __syncthreads();
        for (int idx = tid; idx < CDIM * CDIM; idx += 256) {
            int i = idx >> 6, j = idx & 63;
            float v = cchol[k * CDIM * CDIM + idx];
            T[idx] = (j > i) ? 0.f : (j == i ? expf(v) : v);
        }
        __syncthreads();
        for (int idx = tid; idx < CDIM * CDIM; idx += 256) {
            int i = idx >> 6, j = idx & 63;
            int mmax = (i < j) ? i : j;
            float s = (i == j) ? 1e-6f : 0.f;
            for (int m = 0; m <= mmax; ++m) s += T[i * 64 + m] * T[j * 64 + m];
            Cv[idx] = s;
        }
        __syncthreads();
        for (int c = 0; c < CDIM; ++c) {
            if (tid == 0) Cv[c * 64 + c] = sqrtf(Cv[c * 64 + c]);
            __syncthreads();
            float dinv = 1.f / Cv[c * 64 + c];
            for (int i = c + 1 + tid; i < CDIM; i += 256) Cv[i * 64 + c] *= dinv;
            __syncthreads();
            for (int idx = tid; idx < CDIM * CDIM; idx += 256) {
                int i = idx >> 6, m = idx & 63;
                if (i > c && m > c && m <= i)
                    Cv[i * 64 + m] -= Cv[i * 64 + c] * Cv[m * 64 + c];
            }
            __syncthreads();
        }
        if (tid == 0) {
            float s = 0.f;
            for (int i = 0; i < CDIM; ++i) s += logf(Cv[i * 64 + i]);
            d_logdet[k] = s;
        }
        for (int idx = tid; idx < CDIM * CDIM; idx += 256) T[idx] = 0.f;
        __syncthreads();
        if (tid < CDIM) {
            int c = tid;
            T[c * 64 + c] = 1.f / Cv[c * 64 + c];
            for (int i = c + 1; i < CDIM; ++i) {
                float s = 0.f;
                for (int m = c; m < i; ++m) s += Cv[i * 64 + m] * T[m * 64 + c];
                T[i * 64 + c] = -s / Cv[i * 64 + i];
            }
        }
        __syncthreads();
        for (int idx = tid; idx < CDIM * CDIM; idx += 256) {
            float v = T[idx];
            d_IC[k * CDIM * CDIM + idx] = v;
            d_ICt[k * CDIM * CDIM + idx] = tf32r(v);
        }
        if (tid < CDIM) {
            float s = 0.f;
            for (int j = 0; j < CDIM; ++j) s += T[tid * 64 + j] * means[k * CDIM + j];
            d_mp[k * CDIM + tid] = s;
        }
        __syncthreads();
    }
}

// ---------------------------------------------------------------------------
// d_Wn = tf32(-(IC @ W))
// ---------------------------------------------------------------------------
__global__ void wp_kernel(const float* __restrict__ W)
{
    int c = blockIdx.x, k = blockIdx.y;
    __shared__ float icr[CDIM];
    if (threadIdx.x < CDIM)
        icr[threadIdx.x] = d_IC[k * CDIM * CDIM + c * CDIM + threadIdx.x];
    __syncthreads();
    const float4* W4 = (const float4*)(W + (size_t)k * CDIM * FDIM);
    size_t obase = ((size_t)k * CDIM + c) * FDIM;
    for (int f4 = threadIdx.x; f4 < FDIM / 4; f4 += 256) {
        float4 acc = make_float4(0.f, 0.f, 0.f, 0.f);
        #pragma unroll 8
        for (int c2 = 0; c2 < CDIM; ++c2) {
            float ic = icr[c2];
            float4 wv = W4[c2 * (FDIM / 4) + f4];
            acc.x += ic * wv.x; acc.y += ic * wv.y;
            acc.z += ic * wv.z; acc.w += ic * wv.w;
        }
        d_Wn[obase + f4 * 4 + 0] = tf32r(-acc.x);
        d_Wn[obase + f4 * 4 + 1] = tf32r(-acc.y);
        d_Wn[obase + f4 * 4 + 2] = tf32r(-acc.z);
        d_Wn[obase + f4 * 4 + 3] = tf32r(-acc.w);
    }
}

// ---------------------------------------------------------------------------
// tf32 split of W for the prediction loop
// ---------------------------------------------------------------------------
__global__ void wsplit_kernel(const float* __restrict__ W)
{
    int i = blockIdx.x * 1024 + threadIdx.x * 4;
    #pragma unroll
    for (int j = 0; j < 4; ++j) {
        float v = W[i + j];
        float h = tf32r(v);
        d_Wphi[i + j] = h;
        d_Wplo[i + j] = tf32r(v - h);
    }
}

// ---------------------------------------------------------------------------
// window init: frames 0..63 = emissions (split)
// ---------------------------------------------------------------------------
__global__ void win_init_kernel(const float* __restrict__ em)
{
    int b = blockIdx.x;
    for (int i = threadIdx.x; i < FDIM; i += 256) {
        float v = em[(size_t)b * FDIM + i];
        float h = tf32r(v);
        d_winhi[(size_t)b * 5120 + i] = h;
        d_winlo[(size_t)b * 5120 + i] = tf32r(v - h);
    }
}

// ---------------------------------------------------------------------------
// elp GEMM: CTA = (2 batches, state k). M=128, N=64, K=4160 (64 W chunks + IC)
// smem: A [2][128][AST] f32 (17408 fl), B [2 stages][64][AST] (8704 fl)
// ---------------------------------------------------------------------------
#define GA_FLOATS 17408
#define GB_FLOATS 8704
#define GSMEM_BYTES ((GA_FLOATS + GB_FLOATS) * 4)

extern __shared__ float smf[];

__device__ __forceinline__ void g_fill_B(int l, int stage, int k,
                                         uint32_t sb, int tid)
{
    uint32_t base = sb + (GA_FLOATS + stage * 4352) * 4;
    for (int idx = tid; idx < 1024; idx += 256) {
        int n = idx >> 4, q = idx & 15;
        const float* src = (l < 64)
            ? d_Wn + ((size_t)(k * 64 + n)) * FDIM + l * 64 + q * 4
            : d_ICt + (k * 64 + n) * 64 + q * 4;
        cpa16(base + n * (AST * 4) + q * 16, src);
    }
    CP_COMMIT();
}

__global__ __launch_bounds__(256, 2) void gemm_elp(const float* __restrict__ em)
{
    uint32_t sb = smem_u32(smf);
    int tid = threadIdx.x;
    int wid = tid >> 5, lane = tid & 31;
    int g = lane >> 2, q4 = lane & 3;
    int bx = blockIdx.x, k = blockIdx.y;
    int b0 = bx * 2;

    g_fill_B(0, 0, k, sb, tid);

    // A panel: rows 0..63 zero, rows 64..127 = emissions (tf32-rounded)
    for (int idx = tid; idx < 2 * 64 * 17; idx += 256) {
        int b = idx / (64 * 17); int r = (idx / 17) & 63; int q = idx % 17;
        float4 z = make_float4(0.f, 0.f, 0.f, 0.f);
        *(float4*)(smf + b * 128 * AST + r * AST + q * 4) = z;
    }
    for (int idx = tid; idx < 2 * 64 * 16; idx += 256) {
        int b = idx >> 10; int t = (idx >> 4) & 63; int q = idx & 15;
        float4 v = *(const float4*)(em + (((size_t)(b0 + b)) * 64 + t) * 64 + q * 4);
        float4 o = make_float4(tf32r(v.x), tf32r(v.y), tf32r(v.z), tf32r(v.w));
        *(float4*)(smf + b * 128 * AST + (64 + t) * AST + q * 4) = o;
    }

    int warpM = wid >> 1, warpN = wid & 1;
    int bp = warpM >> 1;
    int tb = (warpM & 1) * 32;
    const float* Ab = smf + bp * 128 * AST;

    float C[2][4][4];
    #pragma unroll
    for (int mt = 0; mt < 2; ++mt)
        #pragma unroll
        for (int nt = 0; nt < 4; ++nt)
            #pragma unroll
            for (int i = 0; i < 4; ++i) C[mt][nt][i] = 0.f;

    for (int l = 0; l <= 64; ++l) {
        int s = l & 1;
        if (l < 64) { g_fill_B(l + 1, s ^ 1, k, sb, tid); CP_WAIT1(); }
        else        { CP_WAIT0(); }
        __syncthreads();

        const float* Bs = smf + GA_FLOATS + s * 4352;
        int fbase = tb + l + g;
        #pragma unroll
        for (int st = 0; st < 8; ++st) {
            int c = q4 + st * 8;
            uint32_t A0[2][4];
            #pragma unroll
            for (int mt = 0; mt < 2; ++mt) {
                const float* ar = Ab + (fbase + mt * 16) * AST;
                A0[mt][0] = __float_as_uint(ar[c]);
                A0[mt][1] = __float_as_uint(ar[8 * AST + c]);
                A0[mt][2] = __float_as_uint(ar[c + 4]);
                A0[mt][3] = __float_as_uint(ar[8 * AST + c + 4]);
            }
            #pragma unroll
            for (int nt = 0; nt < 4; ++nt) {
                int n = warpN * 32 + nt * 8 + g;
                uint32_t bv0 = __float_as_uint(Bs[n * AST + c]);
                uint32_t bv1 = __float_as_uint(Bs[n * AST + c + 4]);
                mma8(C[0][nt], A0[0], bv0, bv1);
                mma8(C[1][nt], A0[1], bv0, bv1);
            }
        }
        __syncthreads();
    }

    // epilogue: quad = sum_cols (D - mp)^2 -> elp
    float* qsm = smf + GA_FLOATS;   // reuse B area (after sync above)
    float ldk = d_logdet[k];
    const float* mpk = d_mp + k * CDIM;

    #pragma unroll
    for (int mt = 0; mt < 2; ++mt) {
        #pragma unroll
        for (int rh = 0; rh < 2; ++rh) {
            float sum = 0.f;
            #pragma unroll
            for (int nt = 0; nt < 4; ++nt) {
                int col = warpN * 32 + nt * 8 + q4 * 2;
                float v0 = C[mt][nt][rh * 2 + 0] - mpk[col];
                float v1 = C[mt][nt][rh * 2 + 1] - mpk[col + 1];
                sum += v0 * v0 + v1 * v1;
            }
            sum += __shfl_xor_sync(0xffffffffu, sum, 1);
            sum += __shfl_xor_sync(0xffffffffu, sum, 2);
            if (q4 == 0) {
                int m = warpM * 32 + mt * 16 + rh * 8 + g;
                qsm[m * 2 + warpN] = sum;
            }
        }
    }
    __syncthreads();
    if (tid < 128) {
        int m = tid;
        float quad = qsm[m * 2] + qsm[m * 2 + 1];
        int b = b0 + (m >= 64), t = m & 63;
        const float C_LOG2PI = 64.f * 1.8378770664093453f;
        d_elp[(((size_t)b) * 64 + t) * 8 + k] = -0.5f * (C_LOG2PI + quad) - ldk;
    }
}

// ---------------------------------------------------------------------------
// HMM forward scan
// ---------------------------------------------------------------------------
__global__ void forward_kernel()
{
    __shared__ float lt_s[K_ST * K_ST];
    int tid = threadIdx.x;
    for (int i = tid; i < K_ST * K_ST; i += 32) lt_s[i] = d_lt[i];
    __syncthreads();
    int b = blockIdx.x * 32 + tid;
    if (b >= BATCH) return;

    const float* e = d_elp + (size_t)b * LSEQ * K_ST;
    float la[K_ST];
    for (int k = 0; k < K_ST; ++k) la[k] = d_linit[k] + e[k];
    for (int t = 1; t < LSEQ; ++t) {
        const float* et = e + t * K_ST;
        float nla[K_ST];
        #pragma unroll
        for (int k = 0; k < K_ST; ++k) {
            float m = -1e30f;
            #pragma unroll
            for (int j = 0; j < K_ST; ++j) m = fmaxf(m, la[j] + lt_s[j * K_ST + k]);
            float s = 0.f;
            #pragma unroll
            for (int j = 0; j < K_ST; ++j) s += __expf(la[j] + lt_s[j * K_ST + k] - m);
            nla[k] = m + __logf(s) + et[k];
        }
        #pragma unroll
        for (int k = 0; k < K_ST; ++k) la[k] = nla[k];
    }
    int arg = 0; float best = la[0];
    for (int k = 1; k < K_ST; ++k) if (la[k] > best) { best = la[k]; arg = k; }
    int s = d_next[arg];
    for (int p = 0; p < PRED; ++p) { d_states[b * PRED + p] = s; s = d_next[s]; }
}

// ---------------------------------------------------------------------------
// group batches by s0 (= state at step 0); build perm + chain table
// ---------------------------------------------------------------------------
__global__ void group_kernel()
{
    __shared__ int cnt[K_ST], off[K_ST + 1], cur[K_ST];
    int tid = threadIdx.x;
    if (tid < K_ST) { cnt[tid] = 0; cur[tid] = 0; }
    __syncthreads();
    int g = d_states[tid * PRED];
    atomicAdd(&cnt[g], 1);
    __syncthreads();
    if (tid == 0) {
        off[0] = 0;
        for (int i = 0; i < K_ST; ++i) off[i + 1] = off[i] + cnt[i];
    }
    __syncthreads();
    int pos = off[g] + atomicAdd(&cur[g], 1);
    d_perm[pos] = tid;
    if (tid < K_ST) {
        d_gcnt[tid] = cnt[tid];
        d_goff[tid] = off[tid];
        int s = tid;
        for (int p = 0; p < PRED; ++p) { d_chain[tid * PRED + p] = s; s = d_next[s]; }
    }
}

// ---------------------------------------------------------------------------
// pred step p: grouped tf32 GEMM, 3-term split.
// CTA = (group g, 32-batch tile). M=32, N=64, K=4096.
// smem: A [2 stages][2 parts][32][AST] (8704 fl), B [2][2][64][AST] (17408 fl)
// ---------------------------------------------------------------------------
#define PA_FLOATS 8704
#define PB_FLOATS 17408
#define PSMEM_BYTES ((PA_FLOATS + PB_FLOATS) * 4)

__device__ __forceinline__ void p_fill(int j, int stage, int p, int k,
                                       int goff, int cnt, int row0,
                                       uint32_t sb, int tid)
{
    // A: 32 rows x 64 cols, hi+lo
    for (int idx = tid; idx < 1024; idx += 256) {
        int part = idx >> 9, i = (idx >> 4) & 31, q = idx & 15;
        int r = row0 + i; if (r >= cnt) r = row0;
        int b = d_perm[goff + r];
        const float* base = part ? d_winlo : d_winhi;
        const float* src = base + ((size_t)b * 80 + p + j) * 64 + q * 4;
        cpa16(sb + (stage * 4352 + part * 2176 + i * AST) * 4 + q * 16, src);
    }
    // B: 64 rows x 64 cols, hi+lo
    for (int idx = tid; idx < 2048; idx += 256) {
        int part = idx >> 10, n = (idx >> 4) & 63, q = idx & 15;
        const float* base = part ? d_Wplo : d_Wphi;
        const float* src = base + ((size_t)(k * 64 + n)) * FDIM + j * 64 + q * 4;
        cpa16(sb + (PA_FLOATS + stage * 8704 + part * 4352 + n * AST) * 4 + q * 16, src);
    }
    CP_COMMIT();
}

__global__ __launch_bounds__(256, 2) void pred_step(const float* __restrict__ means,
                                                    float* __restrict__ out, int p)
{
    int g = blockIdx.x >> 4, tile = blockIdx.x & 15;
    int cnt = d_gcnt[g];
    int row0 = tile * 32;
    if (row0 >= cnt) return;
    int goff = d_goff[g];
    int k = d_chain[g * PRED + p];

    uint32_t sb = smem_u32(smf);
    int tid = threadIdx.x;
    int wid = tid >> 5, lane = tid & 31;
    int gg = lane >> 2, q4 = lane & 3;
    int warpM = wid >> 2, warpN = wid & 3;

    float C[2][4];
    #pragma unroll
    for (int nt = 0; nt < 2; ++nt)
        #pragma unroll
        for (int i = 0; i < 4; ++i) C[nt][i] = 0.f;

    p_fill(0, 0, p, k, goff, cnt, row0, sb, tid);

    for (int j = 0; j < 64; ++j) {
        int s = j & 1;
        if (j < 63) { p_fill(j + 1, s ^ 1, p, k, goff, cnt, row0, sb, tid); CP_WAIT1(); }
        else        { CP_WAIT0(); }
        __syncthreads();

        const float* Ahi = smf + s * 4352;
        const float* Alo = Ahi + 2176;
        const float* Bhi = smf + PA_FLOATS + s * 8704;
        const float* Blo = Bhi + 4352;
        int r0 = warpM * 16 + gg;

        #pragma unroll
        for (int st = 0; st < 8; ++st) {
            int c = q4 + st * 8;
            uint32_t ah[4], al[4];
            ah[0] = __float_as_uint(Ahi[r0 * AST + c]);
            ah[1] = __float_as_uint(Ahi[(r0 + 8) * AST + c]);
            ah[2] = __float_as_uint(Ahi[r0 * AST + c + 4]);
            ah[3] = __float_as_uint(Ahi[(r0 + 8) * AST + c + 4]);
            al[0] = __float_as_uint(Alo[r0 * AST + c]);
            al[1] = __float_as_uint(Alo[(r0 + 8) * AST + c]);
            al[2] = __float_as_uint(Alo[r0 * AST + c + 4]);
            al[3] = __float_as_uint(Alo[(r0 + 8) * AST + c + 4]);
            #pragma unroll
            for (int nt = 0; nt < 2; ++nt) {
                int n = warpN * 16 + nt * 8 + gg;
                uint32_t bh0 = __float_as_uint(Bhi[n * AST + c]);
                uint32_t bh1 = __float_as_uint(Bhi[n * AST + c + 4]);
                uint32_t bl0 = __float_as_uint(Blo[n * AST + c]);
                uint32_t bl1 = __float_as_uint(Blo[n * AST + c + 4]);
                mma8(C[nt], ah, bh0, bh1);
                mma8(C[nt], ah, bl0, bl1);
                mma8(C[nt], al, bh0, bh1);
            }
        }
        __syncthreads();
    }

    // epilogue: pred = C + means[k]; write out + window (split)
    #pragma unroll
    for (int nt = 0; nt < 2; ++nt) {
        #pragma unroll
        for (int rh = 0; rh < 2; ++rh) {
            int m = warpM * 16 + rh * 8 + gg;
            int r = row0 + m;
            if (r < cnt) {
                int b = d_perm[goff + r];
                #pragma unroll
                for (int cc = 0; cc < 2; ++cc) {
                    int col = warpN * 16 + nt * 8 + q4 * 2 + cc;
                    float val = C[nt][rh * 2 + cc] + means[k * CDIM + col];
                    out[(((size_t)b) * PRED + p) * CDIM + col] = val;
                    float h = tf32r(val);
                    d_winhi[((size_t)b * 80 + 64 + p) * 64 + col] = h;
                    d_winlo[((size_t)b * 80 + 64 + p) * 64 + col] = tf32r(val - h);
                }
            }
        }
    }
}

// ---------------------------------------------------------------------------
extern "C" void kernel_launch(void* const* d_in, const int* in_sizes, int n_in,
                              void* d_out, int out_size)
{
    const float* em    = (const float*)d_in[0];
    const float* tm    = (const float*)d_in[1];
    const float* initd = (const float*)d_in[2];
    const float* means = (const float*)d_in[3];
    const float* cchol = (const float*)d_in[4];
    const float* W     = (const float*)d_in[5];
    float* out = (float*)d_out;

    cudaFuncSetAttribute(gemm_elp, cudaFuncAttributeMaxDynamicSharedMemorySize,
                         GSMEM_BYTES);
    cudaFuncSetAttribute(pred_step, cudaFuncAttributeMaxDynamicSharedMemorySize,
                         PSMEM_BYTES);

    prep_kernel<<<1, 256>>>(tm, initd, cchol, means);
    wsplit_kernel<<<2048, 256>>>(W);
    win_init_kernel<<<512, 256>>>(em);
    wp_kernel<<<dim3(64, 8), 256>>>(W);
    gemm_elp<<<dim3(256, 8), 256, GSMEM_BYTES>>>(em);
    forward_kernel<<<16, 32>>>();
    group_kernel<<<1, 512>>>();
    for (int p = 0; p < PRED; ++p)
        pred_step<<<128, 256, PSMEM_BYTES>>>(means, out, p);
}

// round 6
// speedup vs baseline: 2.9691x; 1.3069x over previous
#include <cuda_runtime.h>
#include <math.h>
#include <stdint.h>

// ---------------------------------------------------------------------------
// LinearAutoregressiveHMM — round 6: launch reorder (gemm_elp -> capture slot),
// split-K x4 prediction loop with deterministic reduce, wp rewritten to read W
// once. Core tf32 mma.sync GEMMs unchanged from the passing r5 kernel.
// ---------------------------------------------------------------------------

#define K_ST   8
#define LSEQ   64
#define CDIM   64
#define BATCH  512
#define PRED   16
#define FDIM   4096
#define AST    68            // padded smem row stride (floats)

// static scratch
__device__ float d_Wn  [K_ST * CDIM * FDIM];   // 8 MB : tf32(-(IC@W))
__device__ float d_ICt [K_ST * CDIM * CDIM];   // tf32(IC)
__device__ float d_IC  [K_ST * CDIM * CDIM];
__device__ float d_mp  [K_ST * CDIM];
__device__ float d_logdet[K_ST];
__device__ float d_lt  [K_ST * K_ST];
__device__ float d_linit[K_ST];
__device__ int   d_next[K_ST];
__device__ float d_elp [BATCH * LSEQ * K_ST];
__device__ int   d_states[BATCH * PRED];
__device__ float d_Wphi[K_ST * CDIM * FDIM];   // 8 MB : tf32 hi of W
__device__ float d_Wplo[K_ST * CDIM * FDIM];   // 8 MB : tf32 lo of W
__device__ float d_winhi[BATCH * 80 * CDIM];   // sliding windows (hi)
__device__ float d_winlo[BATCH * 80 * CDIM];   // (lo)
__device__ int   d_perm[BATCH];
__device__ int   d_goff[K_ST];
__device__ int   d_gcnt[K_ST];
__device__ int   d_chain[K_ST * PRED];
__device__ int   d_bgroup[BATCH];
__device__ float d_part[4][BATCH][CDIM];       // split-K partials (512 KB)

// ---------------------------------------------------------------------------
__device__ __forceinline__ float tf32r(float x) {
    uint32_t u;
    asm("cvt.rna.tf32.f32 %0, %1;" : "=r"(u) : "f"(x));
    return __uint_as_float(u);
}
__device__ __forceinline__ uint32_t smem_u32(const void* p) {
    uint32_t a;
    asm("{ .reg .u64 t; cvta.to.shared.u64 t, %1; cvt.u32.u64 %0, t; }"
        : "=r"(a) : "l"(p));
    return a;
}
__device__ __forceinline__ void cpa16(uint32_t dst, const void* src) {
    asm volatile("cp.async.cg.shared.global [%0], [%1], 16;" :: "r"(dst), "l"(src));
}
#define CP_COMMIT() asm volatile("cp.async.commit_group;" ::: "memory")
#define CP_WAIT1()  asm volatile("cp.async.wait_group 1;" ::: "memory")
#define CP_WAIT0()  asm volatile("cp.async.wait_group 0;" ::: "memory")

__device__ __forceinline__ void mma8(float c[4], const uint32_t a[4],
                                     uint32_t b0, uint32_t b1) {
    asm volatile(
        "mma.sync.aligned.m16n8k8.row.col.f32.tf32.tf32.f32 "
        "{%0,%1,%2,%3},{%4,%5,%6,%7},{%8,%9},{%0,%1,%2,%3};"
        : "+f"(c[0]), "+f"(c[1]), "+f"(c[2]), "+f"(c[3])
        : "r"(a[0]), "r"(a[1]), "r"(a[2]), "r"(a[3]), "r"(b0), "r"(b1));
}

// ---------------------------------------------------------------------------
// prep: small per-state math (softmax, Cholesky, inverse, logdet, mp)
// ---------------------------------------------------------------------------
__global__ void prep_kernel(const float* __restrict__ tm,
                            const float* __restrict__ initd,
                            const float* __restrict__ cchol,
                            const float* __restrict__ means)
{
    __shared__ float T[CDIM * CDIM];
    __shared__ float Cv[CDIM * CDIM];
    int tid = threadIdx.x;

    if (tid < K_ST) {
        float row[K_ST];
        float m = -1e30f;
        for (int j = 0; j < K_ST; ++j) { row[j] = tm[tid * K_ST + j]; m = fmaxf(m, row[j]); }
        float s = 0.f;
        for (int j = 0; j < K_ST; ++j) s += expf(row[j] - m);
        float lse = m + logf(s);
        for (int j = 0; j < K_ST; ++j)
            d_lt[tid * K_ST + j] = logf(expf(row[j] - lse) + 1e-8f);
        int arg = 0; float best = row[0];
        for (int j = 1; j < K_ST; ++j) if (row[j] > best) { best = row[j]; arg = j; }
        d_next[tid] = arg;
    }
    if (tid == 8) {
        float m = -1e30f;
        for (int j = 0; j < K_ST; ++j) m = fmaxf(m, initd[j]);
        float s = 0.f;
        for (int j = 0; j < K_ST; ++j) s += expf(initd[j] - m);
        float lse = m + logf(s);
        for (int j = 0; j < K_ST; ++j) d_linit[j] = initd[j] - lse;
    }

    for (int k = 0; k < K_ST; ++k) {
        __syncthreads();
        for (int idx = tid; idx < CDIM * CDIM; idx += 256) {
            int i = idx >> 6, j = idx & 63;
            float v = cchol[k * CDIM * CDIM + idx];
            T[idx] = (j > i) ? 0.f : (j == i ? expf(v) : v);
        }
        __syncthreads();
        for (int idx = tid; idx < CDIM * CDIM; idx += 256) {
            int i = idx >> 6, j = idx & 63;
            int mmax = (i < j) ? i : j;
            float s = (i == j) ? 1e-6f : 0.f;
            for (int m = 0; m <= mmax; ++m) s += T[i * 64 + m] * T[j * 64 + m];
            Cv[idx] = s;
        }
        __syncthreads();
        for (int c = 0; c < CDIM; ++c) {
            if (tid == 0) Cv[c * 64 + c] = sqrtf(Cv[c * 64 + c]);
            __syncthreads();
            float dinv = 1.f / Cv[c * 64 + c];
            for (int i = c + 1 + tid; i < CDIM; i += 256) Cv[i * 64 + c] *= dinv;
            __syncthreads();
            for (int idx = tid; idx < CDIM * CDIM; idx += 256) {
                int i = idx >> 6, m = idx & 63;
                if (i > c && m > c && m <= i)
                    Cv[i * 64 + m] -= Cv[i * 64 + c] * Cv[m * 64 + c];
            }
            __syncthreads();
        }
        if (tid == 0) {
            float s = 0.f;
            for (int i = 0; i < CDIM; ++i) s += logf(Cv[i * 64 + i]);
            d_logdet[k] = s;
        }
        for (int idx = tid; idx < CDIM * CDIM; idx += 256) T[idx] = 0.f;
        __syncthreads();
        if (tid < CDIM) {
            int c = tid;
            T[c * 64 + c] = 1.f / Cv[c * 64 + c];
            for (int i = c + 1; i < CDIM; ++i) {
                float s = 0.f;
                for (int m = c; m < i; ++m) s += Cv[i * 64 + m] * T[m * 64 + c];
                T[i * 64 + c] = -s / Cv[i * 64 + i];
            }
        }
        __syncthreads();
        for (int idx = tid; idx < CDIM * CDIM; idx += 256) {
            float v = T[idx];
            d_IC[k * CDIM * CDIM + idx] = v;
            d_ICt[k * CDIM * CDIM + idx] = tf32r(v);
        }
        if (tid < CDIM) {
            float s = 0.f;
            for (int j = 0; j < CDIM; ++j) s += T[tid * 64 + j] * means[k * CDIM + j];
            d_mp[k * CDIM + tid] = s;
        }
        __syncthreads();
    }
}

// ---------------------------------------------------------------------------
// wp2: d_Wn = tf32(-(IC@W)), W read once via smem tiles. grid (64 ftiles, 8 k)
// ---------------------------------------------------------------------------
__global__ __launch_bounds__(256) void wp2_kernel(const float* __restrict__ W)
{
    __shared__ float Wt[64 * 65];
    __shared__ float ICs[64 * 65];
    int f0 = blockIdx.x * 64, k = blockIdx.y;
    int tid = threadIdx.x;

    for (int idx = tid; idx < 4096; idx += 256) {
        int c = idx >> 6, c2 = idx & 63;
        ICs[c * 65 + c2] = d_IC[k * 4096 + c * 64 + c2];
        Wt[c * 65 + c2] = W[(size_t)k * CDIM * FDIM + c * FDIM + f0 + c2]; // c==c2row
    }
    __syncthreads();

    int fi = tid & 63, cq = tid >> 6;
    #pragma unroll 4
    for (int t = 0; t < 16; ++t) {
        int c = cq * 16 + t;
        float s = 0.f;
        #pragma unroll 16
        for (int c2 = 0; c2 < 64; ++c2)
            s += ICs[c * 65 + c2] * Wt[c2 * 65 + fi];
        d_Wn[((size_t)(k * 64 + c)) * FDIM + f0 + fi] = tf32r(-s);
    }
}

// ---------------------------------------------------------------------------
// tf32 split of W for the prediction loop
// ---------------------------------------------------------------------------
__global__ void wsplit_kernel(const float* __restrict__ W)
{
    int i = blockIdx.x * 1024 + threadIdx.x * 4;
    #pragma unroll
    for (int j = 0; j < 4; ++j) {
        float v = W[i + j];
        float h = tf32r(v);
        d_Wphi[i + j] = h;
        d_Wplo[i + j] = tf32r(v - h);
    }
}

// ---------------------------------------------------------------------------
// window init: frames 0..63 = emissions (split)
// ---------------------------------------------------------------------------
__global__ void win_init_kernel(const float* __restrict__ em)
{
    int b = blockIdx.x;
    for (int i = threadIdx.x; i < FDIM; i += 256) {
        float v = em[(size_t)b * FDIM + i];
        float h = tf32r(v);
        d_winhi[(size_t)b * 5120 + i] = h;
        d_winlo[(size_t)b * 5120 + i] = tf32r(v - h);
    }
}

// ---------------------------------------------------------------------------
// elp GEMM: CTA = (2 batches, state k). M=128, N=64, K=4160 (64 W chunks + IC)
// ---------------------------------------------------------------------------
#define GA_FLOATS 17408
#define GB_FLOATS 8704
#define GSMEM_BYTES ((GA_FLOATS + GB_FLOATS) * 4)

extern __shared__ float smf[];

__device__ __forceinline__ void g_fill_B(int l, int stage, int k,
                                         uint32_t sb, int tid)
{
    uint32_t base = sb + (GA_FLOATS + stage * 4352) * 4;
    for (int idx = tid; idx < 1024; idx += 256) {
        int n = idx >> 4, q = idx & 15;
        const float* src = (l < 64)
            ? d_Wn + ((size_t)(k * 64 + n)) * FDIM + l * 64 + q * 4
            : d_ICt + (k * 64 + n) * 64 + q * 4;
        cpa16(base + n * (AST * 4) + q * 16, src);
    }
    CP_COMMIT();
}

__global__ __launch_bounds__(256, 2) void gemm_elp(const float* __restrict__ em)
{
    uint32_t sb = smem_u32(smf);
    int tid = threadIdx.x;
    int wid = tid >> 5, lane = tid & 31;
    int g = lane >> 2, q4 = lane & 3;
    int bx = blockIdx.x, k = blockIdx.y;
    int b0 = bx * 2;

    g_fill_B(0, 0, k, sb, tid);

    // A panel: rows 0..63 zero, rows 64..127 = emissions (tf32-rounded)
    for (int idx = tid; idx < 2 * 64 * 17; idx += 256) {
        int b = idx / (64 * 17); int r = (idx / 17) & 63; int q = idx % 17;
        float4 z = make_float4(0.f, 0.f, 0.f, 0.f);
        *(float4*)(smf + b * 128 * AST + r * AST + q * 4) = z;
    }
    for (int idx = tid; idx < 2 * 64 * 16; idx += 256) {
        int b = idx >> 10; int t = (idx >> 4) & 63; int q = idx & 15;
        float4 v = *(const float4*)(em + (((size_t)(b0 + b)) * 64 + t) * 64 + q * 4);
        float4 o = make_float4(tf32r(v.x), tf32r(v.y), tf32r(v.z), tf32r(v.w));
        *(float4*)(smf + b * 128 * AST + (64 + t) * AST + q * 4) = o;
    }

    int warpM = wid >> 1, warpN = wid & 1;
    int bp = warpM >> 1;
    int tb = (warpM & 1) * 32;
    const float* Ab = smf + bp * 128 * AST;

    float C[2][4][4];
    #pragma unroll
    for (int mt = 0; mt < 2; ++mt)
        #pragma unroll
        for (int nt = 0; nt < 4; ++nt)
            #pragma unroll
            for (int i = 0; i < 4; ++i) C[mt][nt][i] = 0.f;

    for (int l = 0; l <= 64; ++l) {
        int s = l & 1;
        if (l < 64) { g_fill_B(l + 1, s ^ 1, k, sb, tid); CP_WAIT1(); }
        else        { CP_WAIT0(); }
        __syncthreads();

        const float* Bs = smf + GA_FLOATS + s * 4352;
        int fbase = tb + l + g;
        #pragma unroll
        for (int st = 0; st < 8; ++st) {
            int c = q4 + st * 8;
            uint32_t A0[2][4];
            #pragma unroll
            for (int mt = 0; mt < 2; ++mt) {
                const float* ar = Ab + (fbase + mt * 16) * AST;
                A0[mt][0] = __float_as_uint(ar[c]);
                A0[mt][1] = __float_as_uint(ar[8 * AST + c]);
                A0[mt][2] = __float_as_uint(ar[c + 4]);
                A0[mt][3] = __float_as_uint(ar[8 * AST + c + 4]);
            }
            #pragma unroll
            for (int nt = 0; nt < 4; ++nt) {
                int n = warpN * 32 + nt * 8 + g;
                uint32_t bv0 = __float_as_uint(Bs[n * AST + c]);
                uint32_t bv1 = __float_as_uint(Bs[n * AST + c + 4]);
                mma8(C[0][nt], A0[0], bv0, bv1);
                mma8(C[1][nt], A0[1], bv0, bv1);
            }
        }
        __syncthreads();
    }

    // epilogue: quad = sum_cols (D - mp)^2 -> elp
    float* qsm = smf + GA_FLOATS;
    float ldk = d_logdet[k];
    const float* mpk = d_mp + k * CDIM;

    #pragma unroll
    for (int mt = 0; mt < 2; ++mt) {
        #pragma unroll
        for (int rh = 0; rh < 2; ++rh) {
            float sum = 0.f;
            #pragma unroll
            for (int nt = 0; nt < 4; ++nt) {
                int col = warpN * 32 + nt * 8 + q4 * 2;
                float v0 = C[mt][nt][rh * 2 + 0] - mpk[col];
                float v1 = C[mt][nt][rh * 2 + 1] - mpk[col + 1];
                sum += v0 * v0 + v1 * v1;
            }
            sum += __shfl_xor_sync(0xffffffffu, sum, 1);
            sum += __shfl_xor_sync(0xffffffffu, sum, 2);
            if (q4 == 0) {
                int m = warpM * 32 + mt * 16 + rh * 8 + g;
                qsm[m * 2 + warpN] = sum;
            }
        }
    }
    __syncthreads();
    if (tid < 128) {
        int m = tid;
        float quad = qsm[m * 2] + qsm[m * 2 + 1];
        int b = b0 + (m >= 64), t = m & 63;
        const float C_LOG2PI = 64.f * 1.8378770664093453f;
        d_elp[(((size_t)b) * 64 + t) * 8 + k] = -0.5f * (C_LOG2PI + quad) - ldk;
    }
}

// ---------------------------------------------------------------------------
// HMM forward scan
// ---------------------------------------------------------------------------
__global__ void forward_kernel()
{
    __shared__ float lt_s[K_ST * K_ST];
    int tid = threadIdx.x;
    for (int i = tid; i < K_ST * K_ST; i += 32) lt_s[i] = d_lt[i];
    __syncthreads();
    int b = blockIdx.x * 32 + tid;
    if (b >= BATCH) return;

    const float* e = d_elp + (size_t)b * LSEQ * K_ST;
    float la[K_ST];
    for (int k = 0; k < K_ST; ++k) la[k] = d_linit[k] + e[k];
    for (int t = 1; t < LSEQ; ++t) {
        const float* et = e + t * K_ST;
        float nla[K_ST];
        #pragma unroll
        for (int k = 0; k < K_ST; ++k) {
            float m = -1e30f;
            #pragma unroll
            for (int j = 0; j < K_ST; ++j) m = fmaxf(m, la[j] + lt_s[j * K_ST + k]);
            float s = 0.f;
            #pragma unroll
            for (int j = 0; j < K_ST; ++j) s += __expf(la[j] + lt_s[j * K_ST + k] - m);
            nla[k] = m + __logf(s) + et[k];
        }
        #pragma unroll
        for (int k = 0; k < K_ST; ++k) la[k] = nla[k];
    }
    int arg = 0; float best = la[0];
    for (int k = 1; k < K_ST; ++k) if (la[k] > best) { best = la[k]; arg = k; }
    int s = d_next[arg];
    for (int p = 0; p < PRED; ++p) { d_states[b * PRED + p] = s; s = d_next[s]; }
}

// ---------------------------------------------------------------------------
// group batches by s0; build perm + chain + per-batch group
// ---------------------------------------------------------------------------
__global__ void group_kernel()
{
    __shared__ int cnt[K_ST], off[K_ST + 1], cur[K_ST];
    int tid = threadIdx.x;
    if (tid < K_ST) { cnt[tid] = 0; cur[tid] = 0; }
    __syncthreads();
    int g = d_states[tid * PRED];
    atomicAdd(&cnt[g], 1);
    __syncthreads();
    if (tid == 0) {
        off[0] = 0;
        for (int i = 0; i < K_ST; ++i) off[i + 1] = off[i] + cnt[i];
    }
    __syncthreads();
    int pos = off[g] + atomicAdd(&cur[g], 1);
    d_perm[pos] = tid;
    d_bgroup[tid] = g;
    if (tid < K_ST) {
        d_gcnt[tid] = cnt[tid];
        d_goff[tid] = off[tid];
        int s = tid;
        for (int p = 0; p < PRED; ++p) { d_chain[tid * PRED + p] = s; s = d_next[s]; }
    }
}

// ---------------------------------------------------------------------------
// pred step p, split-K x4: CTA = (group g, 32-batch tile, ksplit).
// Each CTA covers frames [ks*16, ks*16+16), writes partial C (no means).
// ---------------------------------------------------------------------------
#define PA_FLOATS 8704
#define PB_FLOATS 17408
#define PSMEM_BYTES ((PA_FLOATS + PB_FLOATS) * 4)

__device__ __forceinline__ void p_fill(int j, int stage, int p, int k,
                                       int goff, int cnt, int row0,
                                       uint32_t sb, int tid)
{
    for (int idx = tid; idx < 1024; idx += 256) {
        int part = idx >> 9, i = (idx >> 4) & 31, q = idx & 15;
        int r = row0 + i; if (r >= cnt) r = row0;
        int b = d_perm[goff + r];
        const float* base = part ? d_winlo : d_winhi;
        const float* src = base + ((size_t)b * 80 + p + j) * 64 + q * 4;
        cpa16(sb + (stage * 4352 + part * 2176 + i * AST) * 4 + q * 16, src);
    }
    for (int idx = tid; idx < 2048; idx += 256) {
        int part = idx >> 10, n = (idx >> 4) & 63, q = idx & 15;
        const float* base = part ? d_Wplo : d_Wphi;
        const float* src = base + ((size_t)(k * 64 + n)) * FDIM + j * 64 + q * 4;
        cpa16(sb + (PA_FLOATS + stage * 8704 + part * 4352 + n * AST) * 4 + q * 16, src);
    }
    CP_COMMIT();
}

__global__ __launch_bounds__(256, 2) void pred_stepK(int p)
{
    int ks = blockIdx.x & 3;
    int tile = (blockIdx.x >> 2) & 15;
    int g = blockIdx.x >> 6;
    int cnt = d_gcnt[g];
    int row0 = tile * 32;
    if (row0 >= cnt) return;
    int goff = d_goff[g];
    int k = d_chain[g * PRED + p];

    uint32_t sb = smem_u32(smf);
    int tid = threadIdx.x;
    int wid = tid >> 5, lane = tid & 31;
    int gg = lane >> 2, q4 = lane & 3;
    int warpM = wid >> 2, warpN = wid & 3;

    float C[2][4];
    #pragma unroll
    for (int nt = 0; nt < 2; ++nt)
        #pragma unroll
        for (int i = 0; i < 4; ++i) C[nt][i] = 0.f;

    p_fill(ks * 16, 0, p, k, goff, cnt, row0, sb, tid);

    for (int jj = 0; jj < 16; ++jj) {
        int s = jj & 1;
        if (jj < 15) { p_fill(ks * 16 + jj + 1, s ^ 1, p, k, goff, cnt, row0, sb, tid); CP_WAIT1(); }
        else         { CP_WAIT0(); }
        __syncthreads();

        const float* Ahi = smf + s * 4352;
        const float* Alo = Ahi + 2176;
        const float* Bhi = smf + PA_FLOATS + s * 8704;
        const float* Blo = Bhi + 4352;
        int r0 = warpM * 16 + gg;

        #pragma unroll
        for (int st = 0; st < 8; ++st) {
            int c = q4 + st * 8;
            uint32_t ah[4], al[4];
            ah[0] = __float_as_uint(Ahi[r0 * AST + c]);
            ah[1] = __float_as_uint(Ahi[(r0 + 8) * AST + c]);
            ah[2] = __float_as_uint(Ahi[r0 * AST + c + 4]);
            ah[3] = __float_as_uint(Ahi[(r0 + 8) * AST + c + 4]);
            al[0] = __float_as_uint(Alo[r0 * AST + c]);
            al[1] = __float_as_uint(Alo[(r0 + 8) * AST + c]);
            al[2] = __float_as_uint(Alo[r0 * AST + c + 4]);
            al[3] = __float_as_uint(Alo[(r0 + 8) * AST + c + 4]);
            #pragma unroll
            for (int nt = 0; nt < 2; ++nt) {
                int n = warpN * 16 + nt * 8 + gg;
                uint32_t bh0 = __float_as_uint(Bhi[n * AST + c]);
                uint32_t bh1 = __float_as_uint(Bhi[n * AST + c + 4]);
                uint32_t bl0 = __float_as_uint(Blo[n * AST + c]);
                uint32_t bl1 = __float_as_uint(Blo[n * AST + c + 4]);
                mma8(C[nt], ah, bh0, bh1);
                mma8(C[nt], ah, bl0, bl1);
                mma8(C[nt], al, bh0, bh1);
            }
        }
        __syncthreads();
    }

    #pragma unroll
    for (int nt = 0; nt < 2; ++nt) {
        #pragma unroll
        for (int rh = 0; rh < 2; ++rh) {
            int m = warpM * 16 + rh * 8 + gg;
            int r = row0 + m;
            if (r < cnt) {
                int b = d_perm[goff + r];
                #pragma unroll
                for (int cc = 0; cc < 2; ++cc) {
                    int col = warpN * 16 + nt * 8 + q4 * 2 + cc;
                    d_part[ks][b][col] = C[nt][rh * 2 + cc];
                }
            }
        }
    }
}

// ---------------------------------------------------------------------------
// reduce 4 split-K partials -> out + window update
// ---------------------------------------------------------------------------
__global__ void pred_reduce(const float* __restrict__ means,
                            float* __restrict__ out, int p)
{
    int b = blockIdx.x, col = threadIdx.x;
    int g = d_bgroup[b];
    int k = d_chain[g * PRED + p];
    float v = d_part[0][b][col] + d_part[1][b][col]
            + d_part[2][b][col] + d_part[3][b][col]
            + means[k * CDIM + col];
    out[((size_t)b * PRED + p) * CDIM + col] = v;
    float h = tf32r(v);
    d_winhi[((size_t)b * 80 + 64 + p) * 64 + col] = h;
    d_winlo[((size_t)b * 80 + 64 + p) * 64 + col] = tf32r(v - h);
}

// ---------------------------------------------------------------------------
extern "C" void kernel_launch(void* const* d_in, const int* in_sizes, int n_in,
                              void* d_out, int out_size)
{
    const float* em    = (const float*)d_in[0];
    const float* tm    = (const float*)d_in[1];
    const float* initd = (const float*)d_in[2];
    const float* means = (const float*)d_in[3];
    const float* cchol = (const float*)d_in[4];
    const float* W     = (const float*)d_in[5];
    float* out = (float*)d_out;

    cudaFuncSetAttribute(gemm_elp, cudaFuncAttributeMaxDynamicSharedMemorySize,
                         GSMEM_BYTES);
    cudaFuncSetAttribute(pred_stepK, cudaFuncAttributeMaxDynamicSharedMemorySize,
                         PSMEM_BYTES);

    prep_kernel<<<1, 256>>>(tm, initd, cchol, means);           // 1
    wp2_kernel<<<dim3(64, 8), 256>>>(W);                        // 2
    wsplit_kernel<<<2048, 256>>>(W);                            // 3
    gemm_elp<<<dim3(256, 8), 256, GSMEM_BYTES>>>(em);           // 4 <- ncu slot
    forward_kernel<<<16, 32>>>();                               // 5
    win_init_kernel<<<512, 256>>>(em);                          // 6
    group_kernel<<<1, 512>>>();                                 // 7
    for (int p = 0; p < PRED; ++p) {
        pred_stepK<<<512, 256, PSMEM_BYTES>>>(p);
        pred_reduce<<<512, 64>>>(means, out, p);
    }
}

// round 7
// speedup vs baseline: 5.0500x; 1.7008x over previous
#include <cuda_runtime.h>
#include <math.h>
#include <stdint.h>

// ---------------------------------------------------------------------------
// LinearAutoregressiveHMM — round 7:
//  * pred loop decomposed: parallel emission GEMM (pred_em, all 16 steps at
//    once) + 16 tiny recurrent steps (K=64p) -> kills the 1.6ms serial tail
//  * gemm_elp: K-dim pair permutation -> LDS.64 fragment loads (AST=72)
//  * prep parallelized across the 8 states
// ---------------------------------------------------------------------------

#define K_ST   8
#define LSEQ   64
#define CDIM   64
#define BATCH  512
#define PRED   16
#define FDIM   4096
#define AST    72            // gemm_elp smem stride (floats): 36 ≡ 4 (mod 32) in 8B
#define PST    68            // pred smem stride (floats): scalar-LDS conflict-free

#define COLP(c) (((c) & ~7) | (((c) & 3) << 1) | (((c) & 4) >> 2))

// static scratch
__device__ float d_Wn  [K_ST * CDIM * FDIM];   // tf32(-(IC@W)), K-permuted
__device__ float d_ICt [K_ST * CDIM * CDIM];   // tf32(IC), K-permuted
__device__ float d_IC  [K_ST * CDIM * CDIM];
__device__ float d_mp  [K_ST * CDIM];
__device__ float d_logdet[K_ST];
__device__ float d_lt  [K_ST * K_ST];
__device__ float d_linit[K_ST];
__device__ int   d_next[K_ST];
__device__ float d_elp [BATCH * LSEQ * K_ST];
__device__ int   d_states[BATCH * PRED];
__device__ float d_Wphi[K_ST * CDIM * FDIM];   // tf32 hi of W (unpermuted)
__device__ float d_Wplo[K_ST * CDIM * FDIM];   // tf32 lo of W
__device__ float d_winhi[BATCH * 80 * CDIM];   // frames 0..63 em, 64..79 preds
__device__ float d_winlo[BATCH * 80 * CDIM];
__device__ int   d_perm[BATCH];
__device__ int   d_goff[K_ST];
__device__ int   d_gcnt[K_ST];
__device__ int   d_chain[K_ST * PRED];
__device__ float d_yem[BATCH * PRED * CDIM];   // emission part of preds (2MB)

// ---------------------------------------------------------------------------
__device__ __forceinline__ float tf32r(float x) {
    uint32_t u;
    asm("cvt.rna.tf32.f32 %0, %1;" : "=r"(u) : "f"(x));
    return __uint_as_float(u);
}
__device__ __forceinline__ uint32_t smem_u32(const void* p) {
    uint32_t a;
    asm("{ .reg .u64 t; cvta.to.shared.u64 t, %1; cvt.u32.u64 %0, t; }"
        : "=r"(a) : "l"(p));
    return a;
}
__device__ __forceinline__ void cpa16(uint32_t dst, const void* src) {
    asm volatile("cp.async.cg.shared.global [%0], [%1], 16;" :: "r"(dst), "l"(src));
}
#define CP_COMMIT() asm volatile("cp.async.commit_group;" ::: "memory")
#define CP_WAIT1()  asm volatile("cp.async.wait_group 1;" ::: "memory")
#define CP_WAIT0()  asm volatile("cp.async.wait_group 0;" ::: "memory")

__device__ __forceinline__ void mma8(float c[4], const uint32_t a[4],
                                     uint32_t b0, uint32_t b1) {
    asm volatile(
        "mma.sync.aligned.m16n8k8.row.col.f32.tf32.tf32.f32 "
        "{%0,%1,%2,%3},{%4,%5,%6,%7},{%8,%9},{%0,%1,%2,%3};"
        : "+f"(c[0]), "+f"(c[1]), "+f"(c[2]), "+f"(c[3])
        : "r"(a[0]), "r"(a[1]), "r"(a[2]), "r"(a[3]), "r"(b0), "r"(b1));
}

// ---------------------------------------------------------------------------
// prep_small: softmax/log of transition + init, next[] table. 1 block.
// ---------------------------------------------------------------------------
__global__ void prep_small(const float* __restrict__ tm,
                           const float* __restrict__ initd)
{
    int tid = threadIdx.x;
    if (tid < K_ST) {
        float row[K_ST];
        float m = -1e30f;
        for (int j = 0; j < K_ST; ++j) { row[j] = tm[tid * K_ST + j]; m = fmaxf(m, row[j]); }
        float s = 0.f;
        for (int j = 0; j < K_ST; ++j) s += expf(row[j] - m);
        float lse = m + logf(s);
        for (int j = 0; j < K_ST; ++j)
            d_lt[tid * K_ST + j] = logf(expf(row[j] - lse) + 1e-8f);
        int arg = 0; float best = row[0];
        for (int j = 1; j < K_ST; ++j) if (row[j] > best) { best = row[j]; arg = j; }
        d_next[tid] = arg;
    }
    if (tid == 8) {
        float m = -1e30f;
        for (int j = 0; j < K_ST; ++j) m = fmaxf(m, initd[j]);
        float s = 0.f;
        for (int j = 0; j < K_ST; ++j) s += expf(initd[j] - m);
        float lse = m + logf(s);
        for (int j = 0; j < K_ST; ++j) d_linit[j] = initd[j] - lse;
    }
}

// ---------------------------------------------------------------------------
// prep_chol: one block per state k. covar -> chol -> inverse -> IC/ICt/mp/logdet
// ---------------------------------------------------------------------------
__global__ void prep_chol(const float* __restrict__ cchol,
                          const float* __restrict__ means)
{
    __shared__ float T[CDIM * CDIM];
    __shared__ float Cv[CDIM * CDIM];
    int tid = threadIdx.x;
    int k = blockIdx.x;

    for (int idx = tid; idx < CDIM * CDIM; idx += 256) {
        int i = idx >> 6, j = idx & 63;
        float v = cchol[k * CDIM * CDIM + idx];
        T[idx] = (j > i) ? 0.f : (j == i ? expf(v) : v);
    }
    __syncthreads();
    for (int idx = tid; idx < CDIM * CDIM; idx += 256) {
        int i = idx >> 6, j = idx & 63;
        int mmax = (i < j) ? i : j;
        float s = (i == j) ? 1e-6f : 0.f;
        for (int m = 0; m <= mmax; ++m) s += T[i * 64 + m] * T[j * 64 + m];
        Cv[idx] = s;
    }
    __syncthreads();
    for (int c = 0; c < CDIM; ++c) {
        if (tid == 0) Cv[c * 64 + c] = sqrtf(Cv[c * 64 + c]);
        __syncthreads();
        float dinv = 1.f / Cv[c * 64 + c];
        for (int i = c + 1 + tid; i < CDIM; i += 256) Cv[i * 64 + c] *= dinv;
        __syncthreads();
        for (int idx = tid; idx < CDIM * CDIM; idx += 256) {
            int i = idx >> 6, m = idx & 63;
            if (i > c && m > c && m <= i)
                Cv[i * 64 + m] -= Cv[i * 64 + c] * Cv[m * 64 + c];
        }
        __syncthreads();
    }
    if (tid == 0) {
        float s = 0.f;
        for (int i = 0; i < CDIM; ++i) s += logf(Cv[i * 64 + i]);
        d_logdet[k] = s;
    }
    for (int idx = tid; idx < CDIM * CDIM; idx += 256) T[idx] = 0.f;
    __syncthreads();
    if (tid < CDIM) {
        int c = tid;
        T[c * 64 + c] = 1.f / Cv[c * 64 + c];
        for (int i = c + 1; i < CDIM; ++i) {
            float s = 0.f;
            for (int m = c; m < i; ++m) s += Cv[i * 64 + m] * T[m * 64 + c];
            T[i * 64 + c] = -s / Cv[i * 64 + i];
        }
    }
    __syncthreads();
    for (int idx = tid; idx < CDIM * CDIM; idx += 256) {
        float v = T[idx];
        d_IC[k * CDIM * CDIM + idx] = v;
        d_ICt[k * CDIM * CDIM + (idx & ~63) + COLP(idx & 63)] = tf32r(v);
    }
    if (tid < CDIM) {
        float s = 0.f;
        for (int j = 0; j < CDIM; ++j) s += T[tid * 64 + j] * means[k * CDIM + j];
        d_mp[k * CDIM + tid] = s;
    }
}

// ---------------------------------------------------------------------------
// wp2: d_Wn = tf32(-(IC@W)), K-permuted columns. grid (64 ftiles, 8 k)
// ---------------------------------------------------------------------------
__global__ __launch_bounds__(256) void wp2_kernel(const float* __restrict__ W)
{
    __shared__ float Wt[64 * 65];
    __shared__ float ICs[64 * 65];
    int f0 = blockIdx.x * 64, k = blockIdx.y;
    int tid = threadIdx.x;

    for (int idx = tid; idx < 4096; idx += 256) {
        int c = idx >> 6, c2 = idx & 63;
        ICs[c * 65 + c2] = d_IC[k * 4096 + c * 64 + c2];
        Wt[c * 65 + c2] = W[(size_t)k * CDIM * FDIM + c * FDIM + f0 + c2];
    }
    __syncthreads();

    int fi = tid & 63, cq = tid >> 6;
    #pragma unroll 4
    for (int t = 0; t < 16; ++t) {
        int c = cq * 16 + t;
        float s = 0.f;
        #pragma unroll 16
        for (int c2 = 0; c2 < 64; ++c2)
            s += ICs[c * 65 + c2] * Wt[c2 * 65 + fi];
        d_Wn[((size_t)(k * 64 + c)) * FDIM + f0 + COLP(fi)] = tf32r(-s);
    }
}

// ---------------------------------------------------------------------------
// tf32 split of W (unpermuted; used by pred kernels)
// ---------------------------------------------------------------------------
__global__ void wsplit_kernel(const float* __restrict__ W)
{
    int i = blockIdx.x * 1024 + threadIdx.x * 4;
    #pragma unroll
    for (int j = 0; j < 4; ++j) {
        float v = W[i + j];
        float h = tf32r(v);
        d_Wphi[i + j] = h;
        d_Wplo[i + j] = tf32r(v - h);
    }
}

__global__ void win_init_kernel(const float* __restrict__ em)
{
    int b = blockIdx.x;
    for (int i = threadIdx.x; i < FDIM; i += 256) {
        float v = em[(size_t)b * FDIM + i];
        float h = tf32r(v);
        d_winhi[(size_t)b * 5120 + i] = h;
        d_winlo[(size_t)b * 5120 + i] = tf32r(v - h);
    }
}

// ---------------------------------------------------------------------------
// elp GEMM: CTA = (2 batches, state k). M=128, N=64, K=4160. LDS.64 frags.
// ---------------------------------------------------------------------------
#define GA_FLOATS (2 * 128 * AST)       // 18432
#define GB_STAGE  (64 * AST)            // 4608
#define GSMEM_BYTES ((GA_FLOATS + 2 * GB_STAGE) * 4)

extern __shared__ float smf[];

__device__ __forceinline__ void g_fill_B(int l, int stage, int k,
                                         uint32_t sb, int tid)
{
    uint32_t base = sb + (GA_FLOATS + stage * GB_STAGE) * 4;
    for (int idx = tid; idx < 1024; idx += 256) {
        int n = idx >> 4, q = idx & 15;
        const float* src = (l < 64)
            ? d_Wn + ((size_t)(k * 64 + n)) * FDIM + l * 64 + q * 4
            : d_ICt + (k * 64 + n) * 64 + q * 4;
        cpa16(base + n * (AST * 4) + q * 16, src);
    }
    CP_COMMIT();
}

__global__ __launch_bounds__(256, 2) void gemm_elp(const float* __restrict__ em)
{
    uint32_t sb = smem_u32(smf);
    int tid = threadIdx.x;
    int wid = tid >> 5, lane = tid & 31;
    int g = lane >> 2, q4 = lane & 3;
    int bx = blockIdx.x, k = blockIdx.y;
    int b0 = bx * 2;

    g_fill_B(0, 0, k, sb, tid);

    // A panel: rows 0..63 zero (incl. pad cols), rows 64..127 = em, K-permuted
    for (int idx = tid; idx < 2 * 64 * AST; idx += 256) {
        int b = idx / (64 * AST); int rem = idx - b * 64 * AST;
        smf[b * 128 * AST + rem] = 0.f;
    }
    for (int idx = tid; idx < 8192; idx += 256) {
        int b = idx >> 12, t = (idx >> 6) & 63, c2 = idx & 63;
        float v = em[(((size_t)(b0 + b)) * 64 + t) * 64 + c2];
        smf[b * 128 * AST + (64 + t) * AST + COLP(c2)] = tf32r(v);
    }

    int warpM = wid >> 1, warpN = wid & 1;
    int bp = warpM >> 1;
    int tb = (warpM & 1) * 32;
    const float* Ab = smf + bp * 128 * AST;

    float C[2][4][4];
    #pragma unroll
    for (int mt = 0; mt < 2; ++mt)
        #pragma unroll
        for (int nt = 0; nt < 4; ++nt)
            #pragma unroll
            for (int i = 0; i < 4; ++i) C[mt][nt][i] = 0.f;

    for (int l = 0; l <= 64; ++l) {
        int s = l & 1;
        if (l < 64) { g_fill_B(l + 1, s ^ 1, k, sb, tid); CP_WAIT1(); }
        else        { CP_WAIT0(); }
        __syncthreads();

        const float* Bs = smf + GA_FLOATS + s * GB_STAGE;
        int fbase = tb + l + g;
        #pragma unroll
        for (int st = 0; st < 8; ++st) {
            int cp = st * 8 + 2 * q4;
            uint32_t A0[2][4];
            #pragma unroll
            for (int mt = 0; mt < 2; ++mt) {
                const float* ar = Ab + (fbase + mt * 16) * AST + cp;
                float2 lo = *(const float2*)ar;            // a0, a2
                float2 hi = *(const float2*)(ar + 8 * AST); // a1, a3
                A0[mt][0] = __float_as_uint(lo.x);
                A0[mt][1] = __float_as_uint(hi.x);
                A0[mt][2] = __float_as_uint(lo.y);
                A0[mt][3] = __float_as_uint(hi.y);
            }
            #pragma unroll
            for (int nt = 0; nt < 4; ++nt) {
                int n = warpN * 32 + nt * 8 + g;
                float2 bv = *(const float2*)(Bs + n * AST + cp);
                mma8(C[0][nt], A0[0], __float_as_uint(bv.x), __float_as_uint(bv.y));
                mma8(C[1][nt], A0[1], __float_as_uint(bv.x), __float_as_uint(bv.y));
            }
        }
        __syncthreads();
    }

    // epilogue
    float* qsm = smf + GA_FLOATS;
    float ldk = d_logdet[k];
    const float* mpk = d_mp + k * CDIM;

    #pragma unroll
    for (int mt = 0; mt < 2; ++mt) {
        #pragma unroll
        for (int rh = 0; rh < 2; ++rh) {
            float sum = 0.f;
            #pragma unroll
            for (int nt = 0; nt < 4; ++nt) {
                int col = warpN * 32 + nt * 8 + q4 * 2;
                float v0 = C[mt][nt][rh * 2 + 0] - mpk[col];
                float v1 = C[mt][nt][rh * 2 + 1] - mpk[col + 1];
                sum += v0 * v0 + v1 * v1;
            }
            sum += __shfl_xor_sync(0xffffffffu, sum, 1);
            sum += __shfl_xor_sync(0xffffffffu, sum, 2);
            if (q4 == 0) {
                int m = warpM * 32 + mt * 16 + rh * 8 + g;
                qsm[m * 2 + warpN] = sum;
            }
        }
    }
    __syncthreads();
    if (tid < 128) {
        int m = tid;
        float quad = qsm[m * 2] + qsm[m * 2 + 1];
        int b = b0 + (m >= 64), t = m & 63;
        const float C_LOG2PI = 64.f * 1.8378770664093453f;
        d_elp[(((size_t)b) * 64 + t) * 8 + k] = -0.5f * (C_LOG2PI + quad) - ldk;
    }
}

// ---------------------------------------------------------------------------
// HMM forward scan
// ---------------------------------------------------------------------------
__global__ void forward_kernel()
{
    __shared__ float lt_s[K_ST * K_ST];
    int tid = threadIdx.x;
    for (int i = tid; i < K_ST * K_ST; i += 32) lt_s[i] = d_lt[i];
    __syncthreads();
    int b = blockIdx.x * 32 + tid;
    if (b >= BATCH) return;

    const float* e = d_elp + (size_t)b * LSEQ * K_ST;
    float la[K_ST];
    for (int k = 0; k < K_ST; ++k) la[k] = d_linit[k] + e[k];
    for (int t = 1; t < LSEQ; ++t) {
        const float* et = e + t * K_ST;
        float nla[K_ST];
        #pragma unroll
        for (int k = 0; k < K_ST; ++k) {
            float m = -1e30f;
            #pragma unroll
            for (int j = 0; j < K_ST; ++j) m = fmaxf(m, la[j] + lt_s[j * K_ST + k]);
            float s = 0.f;
            #pragma unroll
            for (int j = 0; j < K_ST; ++j) s += __expf(la[j] + lt_s[j * K_ST + k] - m);
            nla[k] = m + __logf(s) + et[k];
        }
        #pragma unroll
        for (int k = 0; k < K_ST; ++k) la[k] = nla[k];
    }
    int arg = 0; float best = la[0];
    for (int k = 1; k < K_ST; ++k) if (la[k] > best) { best = la[k]; arg = k; }
    int s = d_next[arg];
    for (int p = 0; p < PRED; ++p) { d_states[b * PRED + p] = s; s = d_next[s]; }
}

// ---------------------------------------------------------------------------
// group batches by s0; build perm + chain
// ---------------------------------------------------------------------------
__global__ void group_kernel()
{
    __shared__ int cnt[K_ST], off[K_ST + 1], cur[K_ST];
    int tid = threadIdx.x;
    if (tid < K_ST) { cnt[tid] = 0; cur[tid] = 0; }
    __syncthreads();
    int g = d_states[tid * PRED];
    atomicAdd(&cnt[g], 1);
    __syncthreads();
    if (tid == 0) {
        off[0] = 0;
        for (int i = 0; i < K_ST; ++i) off[i + 1] = off[i] + cnt[i];
    }
    __syncthreads();
    int pos = off[g] + atomicAdd(&cur[g], 1);
    d_perm[pos] = tid;
    if (tid < K_ST) {
        d_gcnt[tid] = cnt[tid];
        d_goff[tid] = off[tid];
        int s = tid;
        for (int p = 0; p < PRED; ++p) { d_chain[tid * PRED + p] = s; s = d_next[s]; }
    }
}

// ---------------------------------------------------------------------------
// pred fill: A = window frame (hi/lo), B = W chunk (hi/lo). PST stride.
// ---------------------------------------------------------------------------
#define PA_FLOATS (2 * 2 * 32 * PST)    // 8704
#define PB_STAGE  (2 * 64 * PST)        // 8704
#define PSMEM_BYTES ((PA_FLOATS + 2 * PB_STAGE) * 4)

__device__ __forceinline__ void p_fill2(int aframe, int bchunk, int stage, int k,
                                        int goff, int cnt, int row0,
                                        uint32_t sb, int tid)
{
    for (int idx = tid; idx < 1024; idx += 256) {
        int part = idx >> 9, i = (idx >> 4) & 31, q = idx & 15;
        int r = row0 + i; if (r >= cnt) r = row0;
        int b = d_perm[goff + r];
        const float* base = part ? d_winlo : d_winhi;
        const float* src = base + ((size_t)b * 80 + aframe) * 64 + q * 4;
        cpa16(sb + (stage * (2 * 32 * PST) + part * (32 * PST) + i * PST) * 4 + q * 16, src);
    }
    for (int idx = tid; idx < 2048; idx += 256) {
        int part = idx >> 10, n = (idx >> 4) & 63, q = idx & 15;
        const float* base = part ? d_Wplo : d_Wphi;
        const float* src = base + ((size_t)(k * 64 + n)) * FDIM + bchunk * 64 + q * 4;
        cpa16(sb + (PA_FLOATS + stage * PB_STAGE + part * (64 * PST) + n * PST) * 4 + q * 16, src);
    }
    CP_COMMIT();
}

// shared MMA body for pred kernels: accumulate stage s into C
__device__ __forceinline__ void p_mma(float C[2][4], int s, int warpM, int warpN,
                                      int gg, int q4)
{
    const float* Ahi = smf + s * (2 * 32 * PST);
    const float* Alo = Ahi + 32 * PST;
    const float* Bhi = smf + PA_FLOATS + s * PB_STAGE;
    const float* Blo = Bhi + 64 * PST;
    int r0 = warpM * 16 + gg;

    #pragma unroll
    for (int st = 0; st < 8; ++st) {
        int c = q4 + st * 8;
        uint32_t ah[4], al[4];
        ah[0] = __float_as_uint(Ahi[r0 * PST + c]);
        ah[1] = __float_as_uint(Ahi[(r0 + 8) * PST + c]);
        ah[2] = __float_as_uint(Ahi[r0 * PST + c + 4]);
        ah[3] = __float_as_uint(Ahi[(r0 + 8) * PST + c + 4]);
        al[0] = __float_as_uint(Alo[r0 * PST + c]);
        al[1] = __float_as_uint(Alo[(r0 + 8) * PST + c]);
        al[2] = __float_as_uint(Alo[r0 * PST + c + 4]);
        al[3] = __float_as_uint(Alo[(r0 + 8) * PST + c + 4]);
        #pragma unroll
        for (int nt = 0; nt < 2; ++nt) {
            int n = warpN * 16 + nt * 8 + gg;
            uint32_t bh0 = __float_as_uint(Bhi[n * PST + c]);
            uint32_t bh1 = __float_as_uint(Bhi[n * PST + c + 4]);
            uint32_t bl0 = __float_as_uint(Blo[n * PST + c]);
            uint32_t bl1 = __float_as_uint(Blo[n * PST + c + 4]);
            mma8(C[nt], ah, bh0, bh1);
            mma8(C[nt], ah, bl0, bl1);
            mma8(C[nt], al, bh0, bh1);
        }
    }
}

// ---------------------------------------------------------------------------
// pred_em: emission part of ALL 16 steps in parallel.
// grid (g*16+tile, p). K = (64-p)*64; chunk j: A frame p+j, B chunk j.
// ---------------------------------------------------------------------------
__global__ __launch_bounds__(256, 2) void pred_em()
{
    int p = blockIdx.y;
    int g = blockIdx.x >> 4, tile = blockIdx.x & 15;
    int cnt = d_gcnt[g];
    int row0 = tile * 32;
    if (row0 >= cnt) return;
    int goff = d_goff[g];
    int k = d_chain[g * PRED + p];

    uint32_t sb = smem_u32(smf);
    int tid = threadIdx.x;
    int wid = tid >> 5, lane = tid & 31;
    int gg = lane >> 2, q4 = lane & 3;
    int warpM = wid >> 2, warpN = wid & 3;

    float C[2][4];
    #pragma unroll
    for (int nt = 0; nt < 2; ++nt)
        #pragma unroll
        for (int i = 0; i < 4; ++i) C[nt][i] = 0.f;

    int nchunks = 64 - p;
    p_fill2(p, 0, 0, k, goff, cnt, row0, sb, tid);
    for (int j = 0; j < nchunks; ++j) {
        int s = j & 1;
        if (j < nchunks - 1) {
            p_fill2(p + j + 1, j + 1, s ^ 1, k, goff, cnt, row0, sb, tid);
            CP_WAIT1();
        } else CP_WAIT0();
        __syncthreads();
        p_mma(C, s, warpM, warpN, gg, q4);
        __syncthreads();
    }

    #pragma unroll
    for (int nt = 0; nt < 2; ++nt)
        #pragma unroll
        for (int rh = 0; rh < 2; ++rh) {
            int m = warpM * 16 + rh * 8 + gg;
            int r = row0 + m;
            if (r < cnt) {
                int b = d_perm[goff + r];
                #pragma unroll
                for (int cc = 0; cc < 2; ++cc) {
                    int col = warpN * 16 + nt * 8 + q4 * 2 + cc;
                    d_yem[((size_t)b * PRED + p) * CDIM + col] = C[nt][rh * 2 + cc];
                }
            }
        }
}

// ---------------------------------------------------------------------------
// pred_rec step p: recurrent part (K = 64*p) + finalize.
// chunk q: A frame 64+q (prev preds), B chunk 64-p+q.
// ---------------------------------------------------------------------------
__global__ __launch_bounds__(256, 2) void pred_rec(const float* __restrict__ means,
                                                   float* __restrict__ out, int p)
{
    int g = blockIdx.x >> 4, tile = blockIdx.x & 15;
    int cnt = d_gcnt[g];
    int row0 = tile * 32;
    if (row0 >= cnt) return;
    int goff = d_goff[g];
    int k = d_chain[g * PRED + p];

    uint32_t sb = smem_u32(smf);
    int tid = threadIdx.x;
    int wid = tid >> 5, lane = tid & 31;
    int gg = lane >> 2, q4 = lane & 3;
    int warpM = wid >> 2, warpN = wid & 3;

    float C[2][4];
    #pragma unroll
    for (int nt = 0; nt < 2; ++nt)
        #pragma unroll
        for (int i = 0; i < 4; ++i) C[nt][i] = 0.f;

    if (p > 0) {
        p_fill2(64, 64 - p, 0, k, goff, cnt, row0, sb, tid);
        for (int q = 0; q < p; ++q) {
            int s = q & 1;
            if (q < p - 1) {
                p_fill2(64 + q + 1, 64 - p + q + 1, s ^ 1, k, goff, cnt, row0, sb, tid);
                CP_WAIT1();
            } else CP_WAIT0();
            __syncthreads();
            p_mma(C, s, warpM, warpN, gg, q4);
            __syncthreads();
        }
    }

    #pragma unroll
    for (int nt = 0; nt < 2; ++nt)
        #pragma unroll
        for (int rh = 0; rh < 2; ++rh) {
            int m = warpM * 16 + rh * 8 + gg;
            int r = row0 + m;
            if (r < cnt) {
                int b = d_perm[goff + r];
                #pragma unroll
                for (int cc = 0; cc < 2; ++cc) {
                    int col = warpN * 16 + nt * 8 + q4 * 2 + cc;
                    float v = C[nt][rh * 2 + cc]
                            + d_yem[((size_t)b * PRED + p) * CDIM + col]
                            + means[k * CDIM + col];
                    out[((size_t)b * PRED + p) * CDIM + col] = v;
                    float h = tf32r(v);
                    d_winhi[((size_t)b * 80 + 64 + p) * 64 + col] = h;
                    d_winlo[((size_t)b * 80 + 64 + p) * 64 + col] = tf32r(v - h);
                }
            }
        }
}

// ---------------------------------------------------------------------------
extern "C" void kernel_launch(void* const* d_in, const int* in_sizes, int n_in,
                              void* d_out, int out_size)
{
    const float* em    = (const float*)d_in[0];
    const float* tm    = (const float*)d_in[1];
    const float* initd = (const float*)d_in[2];
    const float* means = (const float*)d_in[3];
    const float* cchol = (const float*)d_in[4];
    const float* W     = (const float*)d_in[5];
    float* out = (float*)d_out;

    cudaFuncSetAttribute(gemm_elp, cudaFuncAttributeMaxDynamicSharedMemorySize,
                         GSMEM_BYTES);
    cudaFuncSetAttribute(pred_em, cudaFuncAttributeMaxDynamicSharedMemorySize,
                         PSMEM_BYTES);
    cudaFuncSetAttribute(pred_rec, cudaFuncAttributeMaxDynamicSharedMemorySize,
                         PSMEM_BYTES);

    prep_small<<<1, 32>>>(tm, initd);                           // 1
    prep_chol<<<8, 256>>>(cchol, means);                        // 2
    wp2_kernel<<<dim3(64, 8), 256>>>(W);                        // 3
    gemm_elp<<<dim3(256, 8), 256, GSMEM_BYTES>>>(em);           // 4 <- ncu slot
    forward_kernel<<<16, 32>>>();                               // 5
    wsplit_kernel<<<2048, 256>>>(W);                            // 6
    win_init_kernel<<<512, 256>>>(em);                          // 7
    group_kernel<<<1, 512>>>();                                 // 8
    pred_em<<<dim3(128, 16), 256, PSMEM_BYTES>>>();             // 9
    for (int p = 0; p < PRED; ++p)
        pred_rec<<<128, 256, PSMEM_BYTES>>>(means, out, p);
}

// round 8
// speedup vs baseline: 5.4924x; 1.0876x over previous
#include <cuda_runtime.h>
#include <math.h>
#include <stdint.h>

// ---------------------------------------------------------------------------
// LinearAutoregressiveHMM — round 8:
//  * gemm_elp reverted to r6 scalar-fragment codegen (the r7 LDS.64 permute
//    regressed it) + NEW: Toeplitz zero-block skipping — 38.5% of MMA tiles
//    multiply all-zero padding rows and are now predicated off.
//  * pred decomposition (pred_em parallel + 16 tiny pred_rec) kept from r7.
// ---------------------------------------------------------------------------

#define K_ST   8
#define LSEQ   64
#define CDIM   64
#define BATCH  512
#define PRED   16
#define FDIM   4096
#define AST    68            // smem row stride (floats)
#define PST    68

// static scratch
__device__ float d_Wn  [K_ST * CDIM * FDIM];   // tf32(-(IC@W))
__device__ float d_ICt [K_ST * CDIM * CDIM];   // tf32(IC)
__device__ float d_IC  [K_ST * CDIM * CDIM];
__device__ float d_mp  [K_ST * CDIM];
__device__ float d_logdet[K_ST];
__device__ float d_lt  [K_ST * K_ST];
__device__ float d_linit[K_ST];
__device__ int   d_next[K_ST];
__device__ float d_elp [BATCH * LSEQ * K_ST];
__device__ int   d_states[BATCH * PRED];
__device__ float d_Wphi[K_ST * CDIM * FDIM];
__device__ float d_Wplo[K_ST * CDIM * FDIM];
__device__ float d_winhi[BATCH * 80 * CDIM];
__device__ float d_winlo[BATCH * 80 * CDIM];
__device__ int   d_perm[BATCH];
__device__ int   d_goff[K_ST];
__device__ int   d_gcnt[K_ST];
__device__ int   d_chain[K_ST * PRED];
__device__ float d_yem[BATCH * PRED * CDIM];

// ---------------------------------------------------------------------------
__device__ __forceinline__ float tf32r(float x) {
    uint32_t u;
    asm("cvt.rna.tf32.f32 %0, %1;" : "=r"(u) : "f"(x));
    return __uint_as_float(u);
}
__device__ __forceinline__ uint32_t smem_u32(const void* p) {
    uint32_t a;
    asm("{ .reg .u64 t; cvta.to.shared.u64 t, %1; cvt.u32.u64 %0, t; }"
        : "=r"(a) : "l"(p));
    return a;
}
__device__ __forceinline__ void cpa16(uint32_t dst, const void* src) {
    asm volatile("cp.async.cg.shared.global [%0], [%1], 16;" :: "r"(dst), "l"(src));
}
#define CP_COMMIT() asm volatile("cp.async.commit_group;" ::: "memory")
#define CP_WAIT1()  asm volatile("cp.async.wait_group 1;" ::: "memory")
#define CP_WAIT0()  asm volatile("cp.async.wait_group 0;" ::: "memory")

__device__ __forceinline__ void mma8(float c[4], const uint32_t a[4],
                                     uint32_t b0, uint32_t b1) {
    asm volatile(
        "mma.sync.aligned.m16n8k8.row.col.f32.tf32.tf32.f32 "
        "{%0,%1,%2,%3},{%4,%5,%6,%7},{%8,%9},{%0,%1,%2,%3};"
        : "+f"(c[0]), "+f"(c[1]), "+f"(c[2]), "+f"(c[3])
        : "r"(a[0]), "r"(a[1]), "r"(a[2]), "r"(a[3]), "r"(b0), "r"(b1));
}

// ---------------------------------------------------------------------------
__global__ void prep_small(const float* __restrict__ tm,
                           const float* __restrict__ initd)
{
    int tid = threadIdx.x;
    if (tid < K_ST) {
        float row[K_ST];
        float m = -1e30f;
        for (int j = 0; j < K_ST; ++j) { row[j] = tm[tid * K_ST + j]; m = fmaxf(m, row[j]); }
        float s = 0.f;
        for (int j = 0; j < K_ST; ++j) s += expf(row[j] - m);
        float lse = m + logf(s);
        for (int j = 0; j < K_ST; ++j)
            d_lt[tid * K_ST + j] = logf(expf(row[j] - lse) + 1e-8f);
        int arg = 0; float best = row[0];
        for (int j = 1; j < K_ST; ++j) if (row[j] > best) { best = row[j]; arg = j; }
        d_next[tid] = arg;
    }
    if (tid == 8) {
        float m = -1e30f;
        for (int j = 0; j < K_ST; ++j) m = fmaxf(m, initd[j]);
        float s = 0.f;
        for (int j = 0; j < K_ST; ++j) s += expf(initd[j] - m);
        float lse = m + logf(s);
        for (int j = 0; j < K_ST; ++j) d_linit[j] = initd[j] - lse;
    }
}

// ---------------------------------------------------------------------------
__global__ void prep_chol(const float* __restrict__ cchol,
                          const float* __restrict__ means)
{
    __shared__ float T[CDIM * CDIM];
    __shared__ float Cv[CDIM * CDIM];
    int tid = threadIdx.x;
    int k = blockIdx.x;

    for (int idx = tid; idx < CDIM * CDIM; idx += 256) {
        int i = idx >> 6, j = idx & 63;
        float v = cchol[k * CDIM * CDIM + idx];
        T[idx] = (j > i) ? 0.f : (j == i ? expf(v) : v);
    }
    __syncthreads();
    for (int idx = tid; idx < CDIM * CDIM; idx += 256) {
        int i = idx >> 6, j = idx & 63;
        int mmax = (i < j) ? i : j;
        float s = (i == j) ? 1e-6f : 0.f;
        for (int m = 0; m <= mmax; ++m) s += T[i * 64 + m] * T[j * 64 + m];
        Cv[idx] = s;
    }
    __syncthreads();
    for (int c = 0; c < CDIM; ++c) {
        if (tid == 0) Cv[c * 64 + c] = sqrtf(Cv[c * 64 + c]);
        __syncthreads();
        float dinv = 1.f / Cv[c * 64 + c];
        for (int i = c + 1 + tid; i < CDIM; i += 256) Cv[i * 64 + c] *= dinv;
        __syncthreads();
        for (int idx = tid; idx < CDIM * CDIM; idx += 256) {
            int i = idx >> 6, m = idx & 63;
            if (i > c && m > c && m <= i)
                Cv[i * 64 + m] -= Cv[i * 64 + c] * Cv[m * 64 + c];
        }
        __syncthreads();
    }
    if (tid == 0) {
        float s = 0.f;
        for (int i = 0; i < CDIM; ++i) s += logf(Cv[i * 64 + i]);
        d_logdet[k] = s;
    }
    for (int idx = tid; idx < CDIM * CDIM; idx += 256) T[idx] = 0.f;
    __syncthreads();
    if (tid < CDIM) {
        int c = tid;
        T[c * 64 + c] = 1.f / Cv[c * 64 + c];
        for (int i = c + 1; i < CDIM; ++i) {
            float s = 0.f;
            for (int m = c; m < i; ++m) s += Cv[i * 64 + m] * T[m * 64 + c];
            T[i * 64 + c] = -s / Cv[i * 64 + i];
        }
    }
    __syncthreads();
    for (int idx = tid; idx < CDIM * CDIM; idx += 256) {
        float v = T[idx];
        d_IC[k * CDIM * CDIM + idx] = v;
        d_ICt[k * CDIM * CDIM + idx] = tf32r(v);
    }
    if (tid < CDIM) {
        float s = 0.f;
        for (int j = 0; j < CDIM; ++j) s += T[tid * 64 + j] * means[k * CDIM + j];
        d_mp[k * CDIM + tid] = s;
    }
}

// ---------------------------------------------------------------------------
__global__ __launch_bounds__(256) void wp2_kernel(const float* __restrict__ W)
{
    __shared__ float Wt[64 * 65];
    __shared__ float ICs[64 * 65];
    int f0 = blockIdx.x * 64, k = blockIdx.y;
    int tid = threadIdx.x;

    for (int idx = tid; idx < 4096; idx += 256) {
        int c = idx >> 6, c2 = idx & 63;
        ICs[c * 65 + c2] = d_IC[k * 4096 + c * 64 + c2];
        Wt[c * 65 + c2] = W[(size_t)k * CDIM * FDIM + c * FDIM + f0 + c2];
    }
    __syncthreads();

    int fi = tid & 63, cq = tid >> 6;
    #pragma unroll 4
    for (int t = 0; t < 16; ++t) {
        int c = cq * 16 + t;
        float s = 0.f;
        #pragma unroll 16
        for (int c2 = 0; c2 < 64; ++c2)
            s += ICs[c * 65 + c2] * Wt[c2 * 65 + fi];
        d_Wn[((size_t)(k * 64 + c)) * FDIM + f0 + fi] = tf32r(-s);
    }
}

// ---------------------------------------------------------------------------
__global__ void wsplit_kernel(const float* __restrict__ W)
{
    int i = blockIdx.x * 1024 + threadIdx.x * 4;
    #pragma unroll
    for (int j = 0; j < 4; ++j) {
        float v = W[i + j];
        float h = tf32r(v);
        d_Wphi[i + j] = h;
        d_Wplo[i + j] = tf32r(v - h);
    }
}

__global__ void win_init_kernel(const float* __restrict__ em)
{
    int b = blockIdx.x;
    for (int i = threadIdx.x; i < FDIM; i += 256) {
        float v = em[(size_t)b * FDIM + i];
        float h = tf32r(v);
        d_winhi[(size_t)b * 5120 + i] = h;
        d_winlo[(size_t)b * 5120 + i] = tf32r(v - h);
    }
}

// ---------------------------------------------------------------------------
// elp GEMM with Toeplitz zero-block skipping.
// ---------------------------------------------------------------------------
#define GA_FLOATS (2 * 128 * AST)       // 17408
#define GB_STAGE  (64 * AST)            // 4352
#define GSMEM_BYTES ((GA_FLOATS + 2 * GB_STAGE) * 4)

extern __shared__ float smf[];

__device__ __forceinline__ void g_fill_B(int l, int stage, int k,
                                         uint32_t sb, int tid)
{
    uint32_t base = sb + (GA_FLOATS + stage * GB_STAGE) * 4;
    for (int idx = tid; idx < 1024; idx += 256) {
        int n = idx >> 4, q = idx & 15;
        const float* src = (l < 64)
            ? d_Wn + ((size_t)(k * 64 + n)) * FDIM + l * 64 + q * 4
            : d_ICt + (k * 64 + n) * 64 + q * 4;
        cpa16(base + n * (AST * 4) + q * 16, src);
    }
    CP_COMMIT();
}

__global__ __launch_bounds__(256, 2) void gemm_elp(const float* __restrict__ em)
{
    uint32_t sb = smem_u32(smf);
    int tid = threadIdx.x;
    int wid = tid >> 5, lane = tid & 31;
    int g = lane >> 2, q4 = lane & 3;
    int bx = blockIdx.x, k = blockIdx.y;
    int b0 = bx * 2;

    g_fill_B(0, 0, k, sb, tid);

    // A panel: rows 0..63 zero, rows 64..127 = emissions (tf32)
    for (int idx = tid; idx < 2 * 64 * 17; idx += 256) {
        int b = idx / (64 * 17); int r = (idx / 17) & 63; int q = idx % 17;
        float4 z = make_float4(0.f, 0.f, 0.f, 0.f);
        *(float4*)(smf + b * 128 * AST + r * AST + q * 4) = z;
    }
    for (int idx = tid; idx < 2 * 64 * 16; idx += 256) {
        int b = idx >> 10; int t = (idx >> 4) & 63; int q = idx & 15;
        float4 v = *(const float4*)(em + (((size_t)(b0 + b)) * 64 + t) * 64 + q * 4);
        float4 o = make_float4(tf32r(v.x), tf32r(v.y), tf32r(v.z), tf32r(v.w));
        *(float4*)(smf + b * 128 * AST + (64 + t) * AST + q * 4) = o;
    }

    int warpM = wid >> 1, warpN = wid & 1;
    int bp = warpM >> 1;
    int tb = (warpM & 1) * 32;
    const float* Ab = smf + bp * 128 * AST;

    float C[2][4][4];
    #pragma unroll
    for (int mt = 0; mt < 2; ++mt)
        #pragma unroll
        for (int nt = 0; nt < 4; ++nt)
            #pragma unroll
            for (int i = 0; i < 4; ++i) C[mt][nt][i] = 0.f;

    for (int l = 0; l <= 64; ++l) {
        int s = l & 1;
        if (l < 64) { g_fill_B(l + 1, s ^ 1, k, sb, tid); CP_WAIT1(); }
        else        { CP_WAIT0(); }
        __syncthreads();

        // Toeplitz zero-skip: A-tile rows [l+tb+16mt, +15] all < 64 -> zero.
        bool act0 = (l + tb) >= 49;   // mt=0 contributes
        bool act1 = (l + tb) >= 33;   // mt=1 contributes (act0 => act1)
        if (act1) {
            const float* Bs = smf + GA_FLOATS + s * GB_STAGE;
            int fbase = tb + l + g;
            #pragma unroll
            for (int st = 0; st < 8; ++st) {
                int c = q4 + st * 8;
                uint32_t A1[4];
                {
                    const float* ar = Ab + (fbase + 16) * AST;
                    A1[0] = __float_as_uint(ar[c]);
                    A1[1] = __float_as_uint(ar[8 * AST + c]);
                    A1[2] = __float_as_uint(ar[c + 4]);
                    A1[3] = __float_as_uint(ar[8 * AST + c + 4]);
                }
                uint32_t A0[4];
                if (act0) {
                    const float* ar = Ab + fbase * AST;
                    A0[0] = __float_as_uint(ar[c]);
                    A0[1] = __float_as_uint(ar[8 * AST + c]);
                    A0[2] = __float_as_uint(ar[c + 4]);
                    A0[3] = __float_as_uint(ar[8 * AST + c + 4]);
                }
                #pragma unroll
                for (int nt = 0; nt < 4; ++nt) {
                    int n = warpN * 32 + nt * 8 + g;
                    uint32_t bv0 = __float_as_uint(Bs[n * AST + c]);
                    uint32_t bv1 = __float_as_uint(Bs[n * AST + c + 4]);
                    if (act0) mma8(C[0][nt], A0, bv0, bv1);
                    mma8(C[1][nt], A1, bv0, bv1);
                }
            }
        }
        __syncthreads();
    }

    // epilogue: quad = sum_cols (D - mp)^2 -> elp
    float* qsm = smf + GA_FLOATS;
    float ldk = d_logdet[k];
    const float* mpk = d_mp + k * CDIM;

    #pragma unroll
    for (int mt = 0; mt < 2; ++mt) {
        #pragma unroll
        for (int rh = 0; rh < 2; ++rh) {
            float sum = 0.f;
            #pragma unroll
            for (int nt = 0; nt < 4; ++nt) {
                int col = warpN * 32 + nt * 8 + q4 * 2;
                float v0 = C[mt][nt][rh * 2 + 0] - mpk[col];
                float v1 = C[mt][nt][rh * 2 + 1] - mpk[col + 1];
                sum += v0 * v0 + v1 * v1;
            }
            sum += __shfl_xor_sync(0xffffffffu, sum, 1);
            sum += __shfl_xor_sync(0xffffffffu, sum, 2);
            if (q4 == 0) {
                int m = warpM * 32 + mt * 16 + rh * 8 + g;
                qsm[m * 2 + warpN] = sum;
            }
        }
    }
    __syncthreads();
    if (tid < 128) {
        int m = tid;
        float quad = qsm[m * 2] + qsm[m * 2 + 1];
        int b = b0 + (m >= 64), t = m & 63;
        const float C_LOG2PI = 64.f * 1.8378770664093453f;
        d_elp[(((size_t)b) * 64 + t) * 8 + k] = -0.5f * (C_LOG2PI + quad) - ldk;
    }
}

// ---------------------------------------------------------------------------
__global__ void forward_kernel()
{
    __shared__ float lt_s[K_ST * K_ST];
    int tid = threadIdx.x;
    for (int i = tid; i < K_ST * K_ST; i += 32) lt_s[i] = d_lt[i];
    __syncthreads();
    int b = blockIdx.x * 32 + tid;
    if (b >= BATCH) return;

    const float* e = d_elp + (size_t)b * LSEQ * K_ST;
    float la[K_ST];
    for (int k = 0; k < K_ST; ++k) la[k] = d_linit[k] + e[k];
    for (int t = 1; t < LSEQ; ++t) {
        const float* et = e + t * K_ST;
        float nla[K_ST];
        #pragma unroll
        for (int k = 0; k < K_ST; ++k) {
            float m = -1e30f;
            #pragma unroll
            for (int j = 0; j < K_ST; ++j) m = fmaxf(m, la[j] + lt_s[j * K_ST + k]);
            float s = 0.f;
            #pragma unroll
            for (int j = 0; j < K_ST; ++j) s += __expf(la[j] + lt_s[j * K_ST + k] - m);
            nla[k] = m + __logf(s) + et[k];
        }
        #pragma unroll
        for (int k = 0; k < K_ST; ++k) la[k] = nla[k];
    }
    int arg = 0; float best = la[0];
    for (int k = 1; k < K_ST; ++k) if (la[k] > best) { best = la[k]; arg = k; }
    int s = d_next[arg];
    for (int p = 0; p < PRED; ++p) { d_states[b * PRED + p] = s; s = d_next[s]; }
}

// ---------------------------------------------------------------------------
__global__ void group_kernel()
{
    __shared__ int cnt[K_ST], off[K_ST + 1], cur[K_ST];
    int tid = threadIdx.x;
    if (tid < K_ST) { cnt[tid] = 0; cur[tid] = 0; }
    __syncthreads();
    int g = d_states[tid * PRED];
    atomicAdd(&cnt[g], 1);
    __syncthreads();
    if (tid == 0) {
        off[0] = 0;
        for (int i = 0; i < K_ST; ++i) off[i + 1] = off[i] + cnt[i];
    }
    __syncthreads();
    int pos = off[g] + atomicAdd(&cur[g], 1);
    d_perm[pos] = tid;
    if (tid < K_ST) {
        d_gcnt[tid] = cnt[tid];
        d_goff[tid] = off[tid];
        int s = tid;
        for (int p = 0; p < PRED; ++p) { d_chain[tid * PRED + p] = s; s = d_next[s]; }
    }
}

// ---------------------------------------------------------------------------
#define PA_FLOATS (2 * 2 * 32 * PST)    // 8704
#define PB_STAGE  (2 * 64 * PST)        // 8704
#define PSMEM_BYTES ((PA_FLOATS + 2 * PB_STAGE) * 4)

__device__ __forceinline__ void p_fill2(int aframe, int bchunk, int stage, int k,
                                        int goff, int cnt, int row0,
                                        uint32_t sb, int tid)
{
    for (int idx = tid; idx < 1024; idx += 256) {
        int part = idx >> 9, i = (idx >> 4) & 31, q = idx & 15;
        int r = row0 + i; if (r >= cnt) r = row0;
        int b = d_perm[goff + r];
        const float* base = part ? d_winlo : d_winhi;
        const float* src = base + ((size_t)b * 80 + aframe) * 64 + q * 4;
        cpa16(sb + (stage * (2 * 32 * PST) + part * (32 * PST) + i * PST) * 4 + q * 16, src);
    }
    for (int idx = tid; idx < 2048; idx += 256) {
        int part = idx >> 10, n = (idx >> 4) & 63, q = idx & 15;
        const float* base = part ? d_Wplo : d_Wphi;
        const float* src = base + ((size_t)(k * 64 + n)) * FDIM + bchunk * 64 + q * 4;
        cpa16(sb + (PA_FLOATS + stage * PB_STAGE + part * (64 * PST) + n * PST) * 4 + q * 16, src);
    }
    CP_COMMIT();
}

__device__ __forceinline__ void p_mma(float C[2][4], int s, int warpM, int warpN,
                                      int gg, int q4)
{
    const float* Ahi = smf + s * (2 * 32 * PST);
    const float* Alo = Ahi + 32 * PST;
    const float* Bhi = smf + PA_FLOATS + s * PB_STAGE;
    const float* Blo = Bhi + 64 * PST;
    int r0 = warpM * 16 + gg;

    #pragma unroll
    for (int st = 0; st < 8; ++st) {
        int c = q4 + st * 8;
        uint32_t ah[4], al[4];
        ah[0] = __float_as_uint(Ahi[r0 * PST + c]);
        ah[1] = __float_as_uint(Ahi[(r0 + 8) * PST + c]);
        ah[2] = __float_as_uint(Ahi[r0 * PST + c + 4]);
        ah[3] = __float_as_uint(Ahi[(r0 + 8) * PST + c + 4]);
        al[0] = __float_as_uint(Alo[r0 * PST + c]);
        al[1] = __float_as_uint(Alo[(r0 + 8) * PST + c]);
        al[2] = __float_as_uint(Alo[r0 * PST + c + 4]);
        al[3] = __float_as_uint(Alo[(r0 + 8) * PST + c + 4]);
        #pragma unroll
        for (int nt = 0; nt < 2; ++nt) {
            int n = warpN * 16 + nt * 8 + gg;
            uint32_t bh0 = __float_as_uint(Bhi[n * PST + c]);
            uint32_t bh1 = __float_as_uint(Bhi[n * PST + c + 4]);
            uint32_t bl0 = __float_as_uint(Blo[n * PST + c]);
            uint32_t bl1 = __float_as_uint(Blo[n * PST + c + 4]);
            mma8(C[nt], ah, bh0, bh1);
            mma8(C[nt], ah, bl0, bl1);
            mma8(C[nt], al, bh0, bh1);
        }
    }
}

__global__ __launch_bounds__(256, 2) void pred_em()
{
    int p = blockIdx.y;
    int g = blockIdx.x >> 4, tile = blockIdx.x & 15;
    int cnt = d_gcnt[g];
    int row0 = tile * 32;
    if (row0 >= cnt) return;
    int goff = d_goff[g];
    int k = d_chain[g * PRED + p];

    uint32_t sb = smem_u32(smf);
    int tid = threadIdx.x;
    int wid = tid >> 5, lane = tid & 31;
    int gg = lane >> 2, q4 = lane & 3;
    int warpM = wid >> 2, warpN = wid & 3;

    float C[2][4];
    #pragma unroll
    for (int nt = 0; nt < 2; ++nt)
        #pragma unroll
        for (int i = 0; i < 4; ++i) C[nt][i] = 0.f;

    int nchunks = 64 - p;
    p_fill2(p, 0, 0, k, goff, cnt, row0, sb, tid);
    for (int j = 0; j < nchunks; ++j) {
        int s = j & 1;
        if (j < nchunks - 1) {
            p_fill2(p + j + 1, j + 1, s ^ 1, k, goff, cnt, row0, sb, tid);
            CP_WAIT1();
        } else CP_WAIT0();
        __syncthreads();
        p_mma(C, s, warpM, warpN, gg, q4);
        __syncthreads();
    }

    #pragma unroll
    for (int nt = 0; nt < 2; ++nt)
        #pragma unroll
        for (int rh = 0; rh < 2; ++rh) {
            int m = warpM * 16 + rh * 8 + gg;
            int r = row0 + m;
            if (r < cnt) {
                int b = d_perm[goff + r];
                #pragma unroll
                for (int cc = 0; cc < 2; ++cc) {
                    int col = warpN * 16 + nt * 8 + q4 * 2 + cc;
                    d_yem[((size_t)b * PRED + p) * CDIM + col] = C[nt][rh * 2 + cc];
                }
            }
        }
}

__global__ __launch_bounds__(256, 2) void pred_rec(const float* __restrict__ means,
                                                   float* __restrict__ out, int p)
{
    int g = blockIdx.x >> 4, tile = blockIdx.x & 15;
    int cnt = d_gcnt[g];
    int row0 = tile * 32;
    if (row0 >= cnt) return;
    int goff = d_goff[g];
    int k = d_chain[g * PRED + p];

    uint32_t sb = smem_u32(smf);
    int tid = threadIdx.x;
    int wid = tid >> 5, lane = tid & 31;
    int gg = lane >> 2, q4 = lane & 3;
    int warpM = wid >> 2, warpN = wid & 3;

    float C[2][4];
    #pragma unroll
    for (int nt = 0; nt < 2; ++nt)
        #pragma unroll
        for (int i = 0; i < 4; ++i) C[nt][i] = 0.f;

    if (p > 0) {
        p_fill2(64, 64 - p, 0, k, goff, cnt, row0, sb, tid);
        for (int q = 0; q < p; ++q) {
            int s = q & 1;
            if (q < p - 1) {
                p_fill2(64 + q + 1, 64 - p + q + 1, s ^ 1, k, goff, cnt, row0, sb, tid);
                CP_WAIT1();
            } else CP_WAIT0();
            __syncthreads();
            p_mma(C, s, warpM, warpN, gg, q4);
            __syncthreads();
        }
    }

    #pragma unroll
    for (int nt = 0; nt < 2; ++nt)
        #pragma unroll
        for (int rh = 0; rh < 2; ++rh) {
            int m = warpM * 16 + rh * 8 + gg;
            int r = row0 + m;
            if (r < cnt) {
                int b = d_perm[goff + r];
                #pragma unroll
                for (int cc = 0; cc < 2; ++cc) {
                    int col = warpN * 16 + nt * 8 + q4 * 2 + cc;
                    float v = C[nt][rh * 2 + cc]
                            + d_yem[((size_t)b * PRED + p) * CDIM + col]
                            + means[k * CDIM + col];
                    out[((size_t)b * PRED + p) * CDIM + col] = v;
                    float h = tf32r(v);
                    d_winhi[((size_t)b * 80 + 64 + p) * 64 + col] = h;
                    d_winlo[((size_t)b * 80 + 64 + p) * 64 + col] = tf32r(v - h);
                }
            }
        }
}

// ---------------------------------------------------------------------------
extern "C" void kernel_launch(void* const* d_in, const int* in_sizes, int n_in,
                              void* d_out, int out_size)
{
    const float* em    = (const float*)d_in[0];
    const float* tm    = (const float*)d_in[1];
    const float* initd = (const float*)d_in[2];
    const float* means = (const float*)d_in[3];
    const float* cchol = (const float*)d_in[4];
    const float* W     = (const float*)d_in[5];
    float* out = (float*)d_out;

    cudaFuncSetAttribute(gemm_elp, cudaFuncAttributeMaxDynamicSharedMemorySize,
                         GSMEM_BYTES);
    cudaFuncSetAttribute(pred_em, cudaFuncAttributeMaxDynamicSharedMemorySize,
                         PSMEM_BYTES);
    cudaFuncSetAttribute(pred_rec, cudaFuncAttributeMaxDynamicSharedMemorySize,
                         PSMEM_BYTES);

    prep_small<<<1, 32>>>(tm, initd);                           // 1
    prep_chol<<<8, 256>>>(cchol, means);                        // 2
    wp2_kernel<<<dim3(64, 8), 256>>>(W);                        // 3
    gemm_elp<<<dim3(256, 8), 256, GSMEM_BYTES>>>(em);           // 4 <- ncu slot
    forward_kernel<<<16, 32>>>();                               // 5
    wsplit_kernel<<<2048, 256>>>(W);                            // 6
    win_init_kernel<<<512, 256>>>(em);                          // 7
    group_kernel<<<1, 512>>>();                                 // 8
    pred_em<<<dim3(128, 16), 256, PSMEM_BYTES>>>();             // 9
    for (int p = 0; p < PRED; ++p)
        pred_rec<<<128, 256, PSMEM_BYTES>>>(means, out, p);
}